// round 11
// baseline (speedup 1.0000x reference)
#include <cuda_runtime.h>
#include <math.h>

#define NLAYER 5
#define EMB 64
#define EMB2 128
#define ATOM_F 32
#define BOND_F 16
#define NN 50000
#define NE 800000
#define PW1 132
#define PW2 68
#define PB 68
#define NCHUNK 49   // ceil(NN/1024)

typedef unsigned long long ull;

// ---------------- scratch (static device globals; no runtime alloc) ----------
__device__ float g_h[NN * EMB];          // row-major [n][64]
__device__ float g_aggr[NN * EMB];       // row-major [n][64] (full GIN base)
__device__ float g_hidT[(size_t)EMB2 * NN];  // transposed [col][n]
__device__ float g_hnT[(size_t)EMB * NN];    // transposed [col][n]
__device__ float g_S[NN * BOND_F];
__device__ float g_stats[2 * EMB];
__device__ int   g_cnt[NN];
__device__ int   g_rowptr[NN + 1];
__device__ int   g_cur[NN];
__device__ int   g_blocksum[NCHUNK];
__device__ int   g_csr[NE];
__device__ int   g_src[NE];

// ---------------- f32x2 packed math ----------------
#define PACK2(d, x) asm("mov.b64 %0, {%1, %1};" : "=l"(d) : "r"(__float_as_uint(x)))
#define FMA2(d, a, b, c) asm("fma.rn.f32x2 %0, %1, %2, %3;" : "=l"(d) : "l"(a), "l"(b), "l"(c))
#define UNPACK2(lo, hi, v)                                            \
    {                                                                 \
        unsigned int u0_, u1_;                                        \
        asm("mov.b64 {%0, %1}, %2;" : "=r"(u0_), "=r"(u1_) : "l"(v)); \
        lo = __uint_as_float(u0_);                                    \
        hi = __uint_as_float(u1_);                                    \
    }

// -------- fused: histogram of dst + h = x @ Wemb^T ------
__global__ __launch_bounds__(256) void hist_embed_kernel(
    const int* __restrict__ ei, const float* __restrict__ x,
    const float* __restrict__ Wemb) {
    __shared__ float w[EMB * ATOM_F];
    int tid = threadIdx.x;
    for (int i = tid; i < EMB * ATOM_F; i += 256) w[i] = Wemb[i];
    __syncthreads();
    int gid = blockIdx.x * 256 + tid;
    if (gid < NE) atomicAdd(&g_cnt[ei[NE + gid]], 1);
    int node = gid >> 4;
    int j0 = (gid & 15) * 4;
    if (node < NN) {
        const float* xr = x + (size_t)node * ATOM_F;
        float a0 = 0.f, a1 = 0.f, a2 = 0.f, a3 = 0.f;
#pragma unroll
        for (int k = 0; k < ATOM_F; k++) {
            float xv = xr[k];
            a0 = fmaf(xv, w[(j0 + 0) * ATOM_F + k], a0);
            a1 = fmaf(xv, w[(j0 + 1) * ATOM_F + k], a1);
            a2 = fmaf(xv, w[(j0 + 2) * ATOM_F + k], a2);
            a3 = fmaf(xv, w[(j0 + 3) * ATOM_F + k], a3);
        }
        *reinterpret_cast<float4*>(&g_h[(size_t)node * EMB + j0]) =
            make_float4(a0, a1, a2, a3);
    }
}

// -------- parallel scan stage 1 --------
__global__ __launch_bounds__(1024) void chunk_scan_kernel() {
    __shared__ int warp_off[32];
    int tid = threadIdx.x;
    int lane = tid & 31, wid = tid >> 5;
    int i = blockIdx.x * 1024 + tid;
    int v = (i < NN) ? g_cnt[i] : 0;
    int x = v;
#pragma unroll
    for (int d = 1; d < 32; d <<= 1) {
        int y = __shfl_up_sync(0xffffffffu, x, d);
        if (lane >= d) x += y;
    }
    if (lane == 31) warp_off[wid] = x;
    __syncthreads();
    if (wid == 0) {
        int w = warp_off[lane];
        int xx = w;
#pragma unroll
        for (int d = 1; d < 32; d <<= 1) {
            int y = __shfl_up_sync(0xffffffffu, xx, d);
            if (lane >= d) xx += y;
        }
        warp_off[lane] = xx - w;
    }
    __syncthreads();
    int excl = warp_off[wid] + x - v;
    if (i < NN) g_rowptr[i] = excl;
    if (tid == 1023) g_blocksum[blockIdx.x] = excl + v;
}

// -------- parallel scan stage 2 --------
__global__ __launch_bounds__(1024) void scan_apply_kernel() {
    __shared__ int s_off;
    int tid = threadIdx.x;
    if (tid == 0) {
        int off = 0;
        for (int j = 0; j < (int)blockIdx.x; j++) off += g_blocksum[j];
        s_off = off;
        if (blockIdx.x == NCHUNK - 1)
            g_rowptr[NN] = off + g_blocksum[NCHUNK - 1];
    }
    __syncthreads();
    int i = blockIdx.x * 1024 + tid;
    if (i < NN) {
        int r = g_rowptr[i] + s_off;
        g_rowptr[i] = r;
        g_cur[i] = r;
    }
}

// ---------------- fill CSR buckets ----------------
__global__ void fill_kernel(const int* __restrict__ ei) {
    int e = blockIdx.x * blockDim.x + threadIdx.x;
    if (e >= NE) return;
    int dst = ei[NE + e];
    int pos = atomicAdd(&g_cur[dst], 1);
    g_csr[pos] = e;
    g_src[pos] = ei[e];
}

// ---------------- S[n] = sum of edge_attr over in-edges (once) ---------------
__global__ void sgather_kernel(const float* __restrict__ ea) {
    int gt = blockIdx.x * blockDim.x + threadIdx.x;
    int node = gt >> 5, lane = gt & 31;
    if (node >= NN) return;
    int beg = g_rowptr[node], end = g_rowptr[node + 1];
    float s = 0.f;
    for (int i = beg; i < end; i += 32) {
        int n = end - i;
        if (n > 32) n = 32;
        int eid = 0;
        if (lane < n) eid = g_csr[i + lane];
        for (int j = 0; j < n; j++) {
            int e = __shfl_sync(0xffffffffu, eid, j);
            if (lane < BOND_F) s += ea[(size_t)e * BOND_F + lane];
        }
    }
    if (lane < BOND_F) g_S[(size_t)node * BOND_F + lane] = s;
}

// ------- per layer: aggr[n] = h[n] + sum_{in} h[src] + deg*be + S@We^T -------
__global__ __launch_bounds__(256) void gather_kernel(
    const float* __restrict__ Wel, const float* __restrict__ bel) {
    __shared__ float sWeT[BOND_F * EMB];  // [k][j]
    __shared__ float sBe[EMB];
    int tid = threadIdx.x;
    for (int idx = tid; idx < BOND_F * EMB; idx += 256) {
        int k = idx >> 6, j = idx & 63;
        sWeT[idx] = Wel[j * BOND_F + k];
    }
    if (tid < EMB) sBe[tid] = bel[tid];
    if (blockIdx.x == 0 && tid < 2 * EMB) g_stats[tid] = 0.f;
    __syncthreads();

    int gt = blockIdx.x * 256 + tid;
    int node = gt >> 5, lane = gt & 31;
    if (node >= NN) return;
    const int half = lane >> 4, sub = lane & 15;
    int beg = g_rowptr[node], end = g_rowptr[node + 1];
    float4 acc0 = make_float4(0.f, 0.f, 0.f, 0.f);
    float4 acc1 = make_float4(0.f, 0.f, 0.f, 0.f);
    if (half == 0)
        acc0 = *reinterpret_cast<const float4*>(&g_h[(size_t)node * EMB + sub * 4]);
    for (int i = beg; i < end; i += 32) {
        int n = end - i;
        if (n > 32) n = 32;
        int src = 0;
        if (lane < n) src = g_src[i + lane];
        int j = 0;
        for (; j + 4 <= n; j += 4) {
            int s0 = __shfl_sync(0xffffffffu, src, j + half);
            int s1 = __shfl_sync(0xffffffffu, src, j + 2 + half);
            float4 v0 = __ldg(reinterpret_cast<const float4*>(
                &g_h[(size_t)s0 * EMB + sub * 4]));
            float4 v1 = __ldg(reinterpret_cast<const float4*>(
                &g_h[(size_t)s1 * EMB + sub * 4]));
            acc0.x += v0.x; acc0.y += v0.y; acc0.z += v0.z; acc0.w += v0.w;
            acc1.x += v1.x; acc1.y += v1.y; acc1.z += v1.z; acc1.w += v1.w;
        }
        if (j + 2 <= n) {
            int s0 = __shfl_sync(0xffffffffu, src, j + half);
            float4 v0 = __ldg(reinterpret_cast<const float4*>(
                &g_h[(size_t)s0 * EMB + sub * 4]));
            acc0.x += v0.x; acc0.y += v0.y; acc0.z += v0.z; acc0.w += v0.w;
            j += 2;
        }
        if (j < n) {
            int s0 = __shfl_sync(0xffffffffu, src, j);
            if (half == 0) {
                float4 v0 = __ldg(reinterpret_cast<const float4*>(
                    &g_h[(size_t)s0 * EMB + sub * 4]));
                acc0.x += v0.x; acc0.y += v0.y; acc0.z += v0.z; acc0.w += v0.w;
            }
        }
    }
    acc0.x += acc1.x; acc0.y += acc1.y; acc0.z += acc1.z; acc0.w += acc1.w;
    acc0.x += __shfl_xor_sync(0xffffffffu, acc0.x, 16);
    acc0.y += __shfl_xor_sync(0xffffffffu, acc0.y, 16);
    acc0.z += __shfl_xor_sync(0xffffffffu, acc0.z, 16);
    acc0.w += __shfl_xor_sync(0xffffffffu, acc0.w, 16);
    if (half == 0) {
        // edge-embed term: deg*be + S @ We^T for cols sub*4..sub*4+3
        float deg = (float)(end - beg + 1);
        const float4* sp =
            reinterpret_cast<const float4*>(&g_S[(size_t)node * BOND_F]);
        float4 s0 = sp[0], s1 = sp[1], s2 = sp[2], s3 = sp[3];
        float se[16] = {s0.x, s0.y, s0.z, s0.w, s1.x, s1.y, s1.z, s1.w,
                        s2.x, s2.y, s2.z, s2.w, s3.x, s3.y, s3.z, s3.w};
        float4 be4 = *reinterpret_cast<const float4*>(&sBe[sub * 4]);
        float4 ee;
        ee.x = deg * be4.x; ee.y = deg * be4.y;
        ee.z = deg * be4.z; ee.w = deg * be4.w;
#pragma unroll
        for (int k = 0; k < BOND_F; k++) {
            float4 w4 = *reinterpret_cast<const float4*>(&sWeT[k * EMB + sub * 4]);
            ee.x = fmaf(se[k], w4.x, ee.x);
            ee.y = fmaf(se[k], w4.y, ee.y);
            ee.z = fmaf(se[k], w4.z, ee.z);
            ee.w = fmaf(se[k], w4.w, ee.w);
        }
        acc0.x += ee.x; acc0.y += ee.y; acc0.z += ee.z; acc0.w += ee.w;
        *reinterpret_cast<float4*>(&g_aggr[(size_t)node * EMB + sub * 4]) = acc0;
    }
}

// ---------- MLP stage B: hidT = relu(base @ W1^T + b1), dual 64-node tiles ---
#define B_SMEM_FLOATS (64 * PW1 + 64 * PB + 128)
#define B_SMEM_BYTES (B_SMEM_FLOATS * 4)

__global__ __launch_bounds__(128) void mlpB_kernel(
    const float* __restrict__ W1l, const float* __restrict__ b1l) {
    extern __shared__ float sm[];
    float* sW1T = sm;                 // [64 k][PW1] cols 0..127
    float* sBase = sW1T + 64 * PW1;   // [64 k][PB] (m contiguous)
    float* sB1 = sBase + 64 * PB;     // 128

    const int tid = threadIdx.x;
    const int blk0 = blockIdx.x * 128;

    for (int idx = tid; idx < EMB2 * EMB; idx += 128) {
        int i = idx >> 6, k = idx & 63;
        sW1T[k * PW1 + i] = W1l[idx];
    }
    if (tid < 128) sB1[tid] = b1l[tid];

    const int rg = tid & 7;          // row octet
    const int c0 = (tid >> 3) * 4;   // col quad (and +64 twin)

#pragma unroll
    for (int t = 0; t < 2; t++) {
        const int node0 = blk0 + t * 64;
        __syncthreads();  // sW1T ready (t=0) / prior tile readers done (t=1)
        // stage base transposed into [k][m]; m fastest for conflict-free STS
#pragma unroll
        for (int i = 0; i < 8; i++) {
            int idx = i * 128 + tid;
            int m = idx & 63, q = idx >> 6;  // q 0..15
            int n = node0 + m;
            float4 v = make_float4(0.f, 0.f, 0.f, 0.f);
            if (n < NN)
                v = *reinterpret_cast<const float4*>(
                    &g_aggr[(size_t)n * EMB + q * 4]);
            sBase[(4 * q + 0) * PB + m] = v.x;
            sBase[(4 * q + 1) * PB + m] = v.y;
            sBase[(4 * q + 2) * PB + m] = v.z;
            sBase[(4 * q + 3) * PB + m] = v.w;
        }
        __syncthreads();

        ull acc[4][8];
#pragma unroll
        for (int r = 0; r < 4; r++)
#pragma unroll
            for (int c = 0; c < 8; c++) acc[r][c] = 0ull;
#pragma unroll 4
        for (int k = 0; k < EMB; k++) {
            ulonglong2 A0 = *reinterpret_cast<const ulonglong2*>(
                &sBase[k * PB + rg * 8]);
            ulonglong2 A1 = *reinterpret_cast<const ulonglong2*>(
                &sBase[k * PB + rg * 8 + 4]);
            float4 wq0 = *reinterpret_cast<const float4*>(&sW1T[k * PW1 + c0]);
            float4 wq1 = *reinterpret_cast<const float4*>(&sW1T[k * PW1 + 64 + c0]);
            ull ap[4] = {A0.x, A0.y, A1.x, A1.y};
            ull ws[8];
            PACK2(ws[0], wq0.x); PACK2(ws[1], wq0.y);
            PACK2(ws[2], wq0.z); PACK2(ws[3], wq0.w);
            PACK2(ws[4], wq1.x); PACK2(ws[5], wq1.y);
            PACK2(ws[6], wq1.z); PACK2(ws[7], wq1.w);
#pragma unroll
            for (int r = 0; r < 4; r++)
#pragma unroll
                for (int c = 0; c < 8; c++)
                    FMA2(acc[r][c], ap[r], ws[c], acc[r][c]);
        }
        int n8 = node0 + rg * 8;
        if (n8 < NN) {
#pragma unroll
            for (int p = 0; p < 8; p++) {
                int col = (p < 4) ? (c0 + p) : (64 + c0 + p - 4);
                float b = sB1[col];
                float l0, h0, l1, h1, l2, h2, l3, h3;
                UNPACK2(l0, h0, acc[0][p]);
                UNPACK2(l1, h1, acc[1][p]);
                UNPACK2(l2, h2, acc[2][p]);
                UNPACK2(l3, h3, acc[3][p]);
                float4 o0 = make_float4(fmaxf(l0 + b, 0.f), fmaxf(h0 + b, 0.f),
                                        fmaxf(l1 + b, 0.f), fmaxf(h1 + b, 0.f));
                float4 o1 = make_float4(fmaxf(l2 + b, 0.f), fmaxf(h2 + b, 0.f),
                                        fmaxf(l3 + b, 0.f), fmaxf(h3 + b, 0.f));
                *reinterpret_cast<float4*>(&g_hidT[(size_t)col * NN + n8]) = o0;
                *reinterpret_cast<float4*>(&g_hidT[(size_t)col * NN + n8 + 4]) = o1;
            }
        }
    }
}

// ---------- MLP stage C: hnT = hid @ W2^T + b2 ; BN stats via shfl ----------
#define C_SMEM_FLOATS (EMB2 * PW2 + 64 * PB + 64)
#define C_SMEM_BYTES (C_SMEM_FLOATS * 4)

__global__ __launch_bounds__(128) void mlpC_kernel(
    const float* __restrict__ W2l, const float* __restrict__ b2l) {
    extern __shared__ float sm[];
    float* sW2T = sm;                  // [128 k][PW2] cols 0..63
    float* sHid = sW2T + EMB2 * PW2;   // [64 k][PB] (m contiguous)
    float* sB2 = sHid + 64 * PB;       // 64

    const int tid = threadIdx.x;
    const int blk0 = blockIdx.x * 128;

    for (int idx = tid; idx < EMB * EMB2; idx += 128) {
        int j = idx >> 7, k = idx & 127;
        sW2T[k * PW2 + j] = W2l[idx];
    }
    if (tid < 64) sB2[tid] = b2l[tid];

    const int rg = tid & 7;
    const int c0 = (tid >> 3) * 4;
    float st[4] = {0.f, 0.f, 0.f, 0.f};
    float sq[4] = {0.f, 0.f, 0.f, 0.f};

#pragma unroll
    for (int t = 0; t < 2; t++) {
        const int node0 = blk0 + t * 64;
        ull acc[4][4];
#pragma unroll
        for (int r = 0; r < 4; r++)
#pragma unroll
            for (int c = 0; c < 4; c++) acc[r][c] = 0ull;

#pragma unroll
        for (int kh = 0; kh < 2; kh++) {
            __syncthreads();  // protect sHid from previous readers / sW2T stage
#pragma unroll
            for (int i = 0; i < 8; i++) {
                int idx = i * 128 + tid;
                int k = idx >> 4, q = idx & 15;
                int n4 = node0 + q * 4;
                float4 v = make_float4(0.f, 0.f, 0.f, 0.f);
                if (n4 < NN)
                    v = *reinterpret_cast<const float4*>(
                        &g_hidT[(size_t)(kh * 64 + k) * NN + n4]);
                *reinterpret_cast<float4*>(&sHid[k * PB + q * 4]) = v;
            }
            __syncthreads();
#pragma unroll 4
            for (int k = 0; k < 64; k++) {
                ulonglong2 A0 = *reinterpret_cast<const ulonglong2*>(
                    &sHid[k * PB + rg * 8]);
                ulonglong2 A1 = *reinterpret_cast<const ulonglong2*>(
                    &sHid[k * PB + rg * 8 + 4]);
                float4 wq = *reinterpret_cast<const float4*>(
                    &sW2T[(kh * 64 + k) * PW2 + c0]);
                ull ap[4] = {A0.x, A0.y, A1.x, A1.y};
                ull ws[4];
                PACK2(ws[0], wq.x); PACK2(ws[1], wq.y);
                PACK2(ws[2], wq.z); PACK2(ws[3], wq.w);
#pragma unroll
                for (int r = 0; r < 4; r++)
#pragma unroll
                    for (int c = 0; c < 4; c++)
                        FMA2(acc[r][c], ap[r], ws[c], acc[r][c]);
            }
        }
        int n8 = node0 + rg * 8;
        if (n8 < NN) {
#pragma unroll
            for (int c = 0; c < 4; c++) {
                int col = c0 + c;
                float b = sB2[col];
                float l0, h0, l1, h1, l2, h2, l3, h3;
                UNPACK2(l0, h0, acc[0][c]);
                UNPACK2(l1, h1, acc[1][c]);
                UNPACK2(l2, h2, acc[2][c]);
                UNPACK2(l3, h3, acc[3][c]);
                l0 += b; h0 += b; l1 += b; h1 += b;
                l2 += b; h2 += b; l3 += b; h3 += b;
                *reinterpret_cast<float4*>(&g_hnT[(size_t)col * NN + n8]) =
                    make_float4(l0, h0, l1, h1);
                *reinterpret_cast<float4*>(&g_hnT[(size_t)col * NN + n8 + 4]) =
                    make_float4(l2, h2, l3, h3);
                st[c] += (l0 + h0) + (l1 + h1) + (l2 + h2) + (l3 + h3);
                sq[c] += l0 * l0 + h0 * h0 + l1 * l1 + h1 * h1 +
                         l2 * l2 + h2 * h2 + l3 * l3 + h3 * h3;
            }
        }
    }
    // reduce stats across the 8 row-groups (lanes differing in low 3 bits)
#pragma unroll
    for (int d = 1; d < 8; d <<= 1) {
#pragma unroll
        for (int c = 0; c < 4; c++) {
            st[c] += __shfl_xor_sync(0xffffffffu, st[c], d);
            sq[c] += __shfl_xor_sync(0xffffffffu, sq[c], d);
        }
    }
    if (rg == 0) {
#pragma unroll
        for (int c = 0; c < 4; c++) {
            atomicAdd(&g_stats[c0 + c], st[c]);
            atomicAdd(&g_stats[EMB + c0 + c], sq[c]);
        }
    }
}

// -------- normalize (+mish), transposed in, row-major out via smem tile -----
template <bool LAST>
__global__ __launch_bounds__(256) void norm_kernel(
    const float* __restrict__ gamma, const float* __restrict__ beta,
    float* __restrict__ outp) {
    __shared__ float sg[EMB], sb[EMB];
    __shared__ float sT[64 * 68];
    int tid = threadIdx.x;
    if (tid < EMB) {
        const float inv = 1.f / (float)NN;
        float mu = g_stats[tid] * inv;
        float var = g_stats[EMB + tid] * inv - mu * mu;
        float rs = rsqrtf(fmaxf(var, 0.f) + 1e-5f);
        float g = rs * gamma[tid];
        sg[tid] = g;
        sb[tid] = beta[tid] - mu * g;
    }
    __syncthreads();
    int node0 = blockIdx.x * 64;
#pragma unroll
    for (int it = 0; it < 4; it++) {
        int idx = it * 256 + tid;
        int ch = idx >> 4, m4 = (idx & 15) * 4;
        int n4 = node0 + m4;
        float4 v = make_float4(0.f, 0.f, 0.f, 0.f);
        if (n4 < NN)
            v = *reinterpret_cast<const float4*>(&g_hnT[(size_t)ch * NN + n4]);
        float vs[4] = {v.x, v.y, v.z, v.w};
        float gch = sg[ch], bch = sb[ch];
#pragma unroll
        for (int q = 0; q < 4; q++) {
            float y = fmaf(vs[q], gch, bch);
            if (!LAST) {
                float t = 1.f + __expf(y);
                y = y - __fdividef(2.f * y, fmaf(t, t, 1.f));
            }
            sT[(m4 + q) * 68 + ch] = y;
        }
    }
    __syncthreads();
    float* dst = LAST ? outp : g_h;
#pragma unroll
    for (int it = 0; it < 4; it++) {
        int idx = it * 256 + tid;
        int m = idx >> 4, c4 = (idx & 15) * 4;
        int n = node0 + m;
        if (n < NN) {
            float4 o = *reinterpret_cast<const float4*>(&sT[m * 68 + c4]);
            *reinterpret_cast<float4*>(&dst[(size_t)n * EMB + c4]) = o;
        }
    }
}

// ---------------- launch ----------------
extern "C" void kernel_launch(void* const* d_in, const int* in_sizes, int n_in,
                              void* d_out, int out_size) {
    const float* x = (const float*)d_in[0];
    const float* ea = (const float*)d_in[1];
    const float* Wemb = (const float*)d_in[2];
    const float* W1 = (const float*)d_in[3];
    const float* b1 = (const float*)d_in[4];
    const float* W2 = (const float*)d_in[5];
    const float* b2 = (const float*)d_in[6];
    const float* We = (const float*)d_in[7];
    const float* be = (const float*)d_in[8];
    const float* gamma = (const float*)d_in[9];
    const float* beta = (const float*)d_in[10];
    const int* ei = (const int*)d_in[11];
    float* out = (float*)d_out;

    cudaFuncSetAttribute(mlpB_kernel, cudaFuncAttributeMaxDynamicSharedMemorySize,
                         B_SMEM_BYTES);
    cudaFuncSetAttribute(mlpC_kernel, cudaFuncAttributeMaxDynamicSharedMemorySize,
                         C_SMEM_BYTES);

    void* cntp = nullptr;
    cudaGetSymbolAddress(&cntp, g_cnt);
    cudaMemsetAsync(cntp, 0, NN * sizeof(int));

    const int nblkD = (NN + 127) / 128;  // dual-tile MLP grid
    const int nblkN = (NN + 63) / 64;    // norm grid

    hist_embed_kernel<<<(NE + 255) / 256, 256>>>(ei, x, Wemb);   // 0
    chunk_scan_kernel<<<NCHUNK, 1024>>>();                       // 1
    scan_apply_kernel<<<NCHUNK, 1024>>>();                       // 2
    // PROBE at launch index 3: new mlpB on steady-state g_aggr (deterministic,
    // overwritten by the real pass) — keeps the MLP kernel under ncu.
    mlpB_kernel<<<nblkD, 128, B_SMEM_BYTES>>>(W1, b1);           // 3 (profiled)
    fill_kernel<<<(NE + 255) / 256, 256>>>(ei);                  // 4
    sgather_kernel<<<(NN * 32 + 255) / 256, 256>>>(ea);          // 5

    for (int l = 0; l < NLAYER; l++) {
        gather_kernel<<<(NN * 32 + 255) / 256, 256>>>(
            We + (size_t)l * EMB * BOND_F, be + (size_t)l * EMB);
        mlpB_kernel<<<nblkD, 128, B_SMEM_BYTES>>>(
            W1 + (size_t)l * EMB2 * EMB, b1 + (size_t)l * EMB2);
        mlpC_kernel<<<nblkD, 128, C_SMEM_BYTES>>>(
            W2 + (size_t)l * EMB * EMB2, b2 + (size_t)l * EMB);
        if (l < NLAYER - 1)
            norm_kernel<false><<<nblkN, 256>>>(
                gamma + (size_t)l * EMB, beta + (size_t)l * EMB, nullptr);
        else
            norm_kernel<true><<<nblkN, 256>>>(
                gamma + (size_t)l * EMB, beta + (size_t)l * EMB, out);
    }
}

// round 12
// speedup vs baseline: 1.1114x; 1.1114x over previous
#include <cuda_runtime.h>
#include <math.h>

#define NLAYER 5
#define EMB 64
#define EMB2 128
#define ATOM_F 32
#define BOND_F 16
#define NN 50000
#define NE 800000
#define PW1 132
#define PW2 68
#define PB 68
#define NCHUNK 49   // ceil(NN/1024)

typedef unsigned long long ull;

// ---------------- scratch (static device globals; no runtime alloc) ----------
__device__ float g_h[NN * EMB];          // row-major [n][64]
__device__ float g_aggr[NN * EMB];       // row-major [n][64] (full GIN base)
__device__ float g_hidT[(size_t)EMB2 * NN];  // transposed [col][n]
__device__ float g_hnT[(size_t)EMB * NN];    // transposed [col][n]
__device__ float g_S[NN * BOND_F];
__device__ float g_stats[2 * EMB];
__device__ int   g_cnt[NN];
__device__ int   g_rowptr[NN + 1];
__device__ int   g_cur[NN];
__device__ int   g_blocksum[NCHUNK];
__device__ int   g_csr[NE];
__device__ int   g_src[NE];

// ---------------- f32x2 packed math ----------------
#define PACK2(d, x) asm("mov.b64 %0, {%1, %1};" : "=l"(d) : "r"(__float_as_uint(x)))
#define FMA2(d, a, b, c) asm("fma.rn.f32x2 %0, %1, %2, %3;" : "=l"(d) : "l"(a), "l"(b), "l"(c))
#define UNPACK2(lo, hi, v)                                            \
    {                                                                 \
        unsigned int u0_, u1_;                                        \
        asm("mov.b64 {%0, %1}, %2;" : "=r"(u0_), "=r"(u1_) : "l"(v)); \
        lo = __uint_as_float(u0_);                                    \
        hi = __uint_as_float(u1_);                                    \
    }

// -------- fused: histogram of dst + h = x @ Wemb^T ------
__global__ __launch_bounds__(256) void hist_embed_kernel(
    const int* __restrict__ ei, const float* __restrict__ x,
    const float* __restrict__ Wemb) {
    __shared__ float w[EMB * ATOM_F];
    int tid = threadIdx.x;
    for (int i = tid; i < EMB * ATOM_F; i += 256) w[i] = Wemb[i];
    __syncthreads();
    int gid = blockIdx.x * 256 + tid;
    if (gid < NE) atomicAdd(&g_cnt[ei[NE + gid]], 1);
    int node = gid >> 4;
    int j0 = (gid & 15) * 4;
    if (node < NN) {
        const float* xr = x + (size_t)node * ATOM_F;
        float a0 = 0.f, a1 = 0.f, a2 = 0.f, a3 = 0.f;
#pragma unroll
        for (int k = 0; k < ATOM_F; k++) {
            float xv = xr[k];
            a0 = fmaf(xv, w[(j0 + 0) * ATOM_F + k], a0);
            a1 = fmaf(xv, w[(j0 + 1) * ATOM_F + k], a1);
            a2 = fmaf(xv, w[(j0 + 2) * ATOM_F + k], a2);
            a3 = fmaf(xv, w[(j0 + 3) * ATOM_F + k], a3);
        }
        *reinterpret_cast<float4*>(&g_h[(size_t)node * EMB + j0]) =
            make_float4(a0, a1, a2, a3);
    }
}

// -------- parallel scan stage 1 --------
__global__ __launch_bounds__(1024) void chunk_scan_kernel() {
    __shared__ int warp_off[32];
    int tid = threadIdx.x;
    int lane = tid & 31, wid = tid >> 5;
    int i = blockIdx.x * 1024 + tid;
    int v = (i < NN) ? g_cnt[i] : 0;
    int x = v;
#pragma unroll
    for (int d = 1; d < 32; d <<= 1) {
        int y = __shfl_up_sync(0xffffffffu, x, d);
        if (lane >= d) x += y;
    }
    if (lane == 31) warp_off[wid] = x;
    __syncthreads();
    if (wid == 0) {
        int w = warp_off[lane];
        int xx = w;
#pragma unroll
        for (int d = 1; d < 32; d <<= 1) {
            int y = __shfl_up_sync(0xffffffffu, xx, d);
            if (lane >= d) xx += y;
        }
        warp_off[lane] = xx - w;
    }
    __syncthreads();
    int excl = warp_off[wid] + x - v;
    if (i < NN) g_rowptr[i] = excl;
    if (tid == 1023) g_blocksum[blockIdx.x] = excl + v;
}

// -------- parallel scan stage 2 --------
__global__ __launch_bounds__(1024) void scan_apply_kernel() {
    __shared__ int s_off;
    int tid = threadIdx.x;
    if (tid == 0) {
        int off = 0;
        for (int j = 0; j < (int)blockIdx.x; j++) off += g_blocksum[j];
        s_off = off;
        if (blockIdx.x == NCHUNK - 1)
            g_rowptr[NN] = off + g_blocksum[NCHUNK - 1];
    }
    __syncthreads();
    int i = blockIdx.x * 1024 + tid;
    if (i < NN) {
        int r = g_rowptr[i] + s_off;
        g_rowptr[i] = r;
        g_cur[i] = r;
    }
}

// ---------------- fill CSR buckets ----------------
__global__ void fill_kernel(const int* __restrict__ ei) {
    int e = blockIdx.x * blockDim.x + threadIdx.x;
    if (e >= NE) return;
    int dst = ei[NE + e];
    int pos = atomicAdd(&g_cur[dst], 1);
    g_csr[pos] = e;
    g_src[pos] = ei[e];
}

// ---------------- S[n] = sum of edge_attr over in-edges (once) ---------------
__global__ void sgather_kernel(const float* __restrict__ ea) {
    int gt = blockIdx.x * blockDim.x + threadIdx.x;
    int node = gt >> 5, lane = gt & 31;
    if (node >= NN) return;
    int beg = g_rowptr[node], end = g_rowptr[node + 1];
    float s = 0.f;
    for (int i = beg; i < end; i += 32) {
        int n = end - i;
        if (n > 32) n = 32;
        int eid = 0;
        if (lane < n) eid = g_csr[i + lane];
        for (int j = 0; j < n; j++) {
            int e = __shfl_sync(0xffffffffu, eid, j);
            if (lane < BOND_F) s += ea[(size_t)e * BOND_F + lane];
        }
    }
    if (lane < BOND_F) g_S[(size_t)node * BOND_F + lane] = s;
}

// ------- per layer: aggr[n] = h[n] + sum_{in} h[src] + deg*be + S@We^T -------
__global__ __launch_bounds__(256) void gather_kernel(
    const float* __restrict__ Wel, const float* __restrict__ bel) {
    __shared__ float sWeT[BOND_F * EMB];  // [k][j]
    __shared__ float sBe[EMB];
    int tid = threadIdx.x;
    for (int idx = tid; idx < BOND_F * EMB; idx += 256) {
        int k = idx >> 6, j = idx & 63;
        sWeT[idx] = Wel[j * BOND_F + k];
    }
    if (tid < EMB) sBe[tid] = bel[tid];
    if (blockIdx.x == 0 && tid < 2 * EMB) g_stats[tid] = 0.f;
    __syncthreads();

    int gt = blockIdx.x * 256 + tid;
    int node = gt >> 5, lane = gt & 31;
    if (node >= NN) return;
    const int half = lane >> 4, sub = lane & 15;
    int beg = g_rowptr[node], end = g_rowptr[node + 1];
    float4 acc0 = make_float4(0.f, 0.f, 0.f, 0.f);
    float4 acc1 = make_float4(0.f, 0.f, 0.f, 0.f);
    if (half == 0)
        acc0 = *reinterpret_cast<const float4*>(&g_h[(size_t)node * EMB + sub * 4]);
    for (int i = beg; i < end; i += 32) {
        int n = end - i;
        if (n > 32) n = 32;
        int src = 0;
        if (lane < n) src = g_src[i + lane];
        int j = 0;
        for (; j + 4 <= n; j += 4) {
            int s0 = __shfl_sync(0xffffffffu, src, j + half);
            int s1 = __shfl_sync(0xffffffffu, src, j + 2 + half);
            float4 v0 = __ldg(reinterpret_cast<const float4*>(
                &g_h[(size_t)s0 * EMB + sub * 4]));
            float4 v1 = __ldg(reinterpret_cast<const float4*>(
                &g_h[(size_t)s1 * EMB + sub * 4]));
            acc0.x += v0.x; acc0.y += v0.y; acc0.z += v0.z; acc0.w += v0.w;
            acc1.x += v1.x; acc1.y += v1.y; acc1.z += v1.z; acc1.w += v1.w;
        }
        if (j + 2 <= n) {
            int s0 = __shfl_sync(0xffffffffu, src, j + half);
            float4 v0 = __ldg(reinterpret_cast<const float4*>(
                &g_h[(size_t)s0 * EMB + sub * 4]));
            acc0.x += v0.x; acc0.y += v0.y; acc0.z += v0.z; acc0.w += v0.w;
            j += 2;
        }
        if (j < n) {
            int s0 = __shfl_sync(0xffffffffu, src, j);
            if (half == 0) {
                float4 v0 = __ldg(reinterpret_cast<const float4*>(
                    &g_h[(size_t)s0 * EMB + sub * 4]));
                acc0.x += v0.x; acc0.y += v0.y; acc0.z += v0.z; acc0.w += v0.w;
            }
        }
    }
    acc0.x += acc1.x; acc0.y += acc1.y; acc0.z += acc1.z; acc0.w += acc1.w;
    acc0.x += __shfl_xor_sync(0xffffffffu, acc0.x, 16);
    acc0.y += __shfl_xor_sync(0xffffffffu, acc0.y, 16);
    acc0.z += __shfl_xor_sync(0xffffffffu, acc0.z, 16);
    acc0.w += __shfl_xor_sync(0xffffffffu, acc0.w, 16);
    if (half == 0) {
        float deg = (float)(end - beg + 1);
        const float4* sp =
            reinterpret_cast<const float4*>(&g_S[(size_t)node * BOND_F]);
        float4 s0 = sp[0], s1 = sp[1], s2 = sp[2], s3 = sp[3];
        float se[16] = {s0.x, s0.y, s0.z, s0.w, s1.x, s1.y, s1.z, s1.w,
                        s2.x, s2.y, s2.z, s2.w, s3.x, s3.y, s3.z, s3.w};
        float4 be4 = *reinterpret_cast<const float4*>(&sBe[sub * 4]);
        float4 ee;
        ee.x = deg * be4.x; ee.y = deg * be4.y;
        ee.z = deg * be4.z; ee.w = deg * be4.w;
#pragma unroll
        for (int k = 0; k < BOND_F; k++) {
            float4 w4 = *reinterpret_cast<const float4*>(&sWeT[k * EMB + sub * 4]);
            ee.x = fmaf(se[k], w4.x, ee.x);
            ee.y = fmaf(se[k], w4.y, ee.y);
            ee.z = fmaf(se[k], w4.z, ee.z);
            ee.w = fmaf(se[k], w4.w, ee.w);
        }
        acc0.x += ee.x; acc0.y += ee.y; acc0.z += ee.z; acc0.w += ee.w;
        *reinterpret_cast<float4*>(&g_aggr[(size_t)node * EMB + sub * 4]) = acc0;
    }
}

// ---------- MLP stage B: hidT = relu(base @ W1^T + b1); 256 thr, 64 nodes ----
#define B_SMEM_FLOATS (64 * PW1 + 64 * PB + 128)
#define B_SMEM_BYTES (B_SMEM_FLOATS * 4)

__global__ __launch_bounds__(256, 3) void mlpB_kernel(
    const float* __restrict__ W1l, const float* __restrict__ b1l) {
    extern __shared__ float sm[];
    float* sW1T = sm;                 // [64 k][PW1] cols 0..127
    float* sBase = sW1T + 64 * PW1;   // [64 k][PB] (m contiguous)
    float* sB1 = sBase + 64 * PB;     // 128

    const int tid = threadIdx.x;
    const int node0 = blockIdx.x * 64;

    for (int idx = tid; idx < EMB2 * EMB; idx += 256) {
        int i = idx >> 6, k = idx & 63;
        sW1T[k * PW1 + i] = W1l[idx];
    }
    if (tid < 128) sB1[tid] = b1l[tid];
#pragma unroll
    for (int i = 0; i < 4; i++) {
        int idx = i * 256 + tid;
        int m = idx & 63, q = idx >> 6;  // q 0..15
        int n = node0 + m;
        float4 v = make_float4(0.f, 0.f, 0.f, 0.f);
        if (n < NN)
            v = *reinterpret_cast<const float4*>(&g_aggr[(size_t)n * EMB + q * 4]);
        sBase[(4 * q + 0) * PB + m] = v.x;
        sBase[(4 * q + 1) * PB + m] = v.y;
        sBase[(4 * q + 2) * PB + m] = v.z;
        sBase[(4 * q + 3) * PB + m] = v.w;
    }
    __syncthreads();

    const int rg = tid & 15;         // rows rg*4 .. rg*4+3
    const int c0 = (tid >> 4) * 8;   // cols c0..c0+7
    ull acc[2][8];
#pragma unroll
    for (int r = 0; r < 2; r++)
#pragma unroll
        for (int c = 0; c < 8; c++) acc[r][c] = 0ull;
#pragma unroll 4
    for (int k = 0; k < EMB; k++) {
        ulonglong2 A = *reinterpret_cast<const ulonglong2*>(&sBase[k * PB + rg * 4]);
        float4 wq0 = *reinterpret_cast<const float4*>(&sW1T[k * PW1 + c0]);
        float4 wq1 = *reinterpret_cast<const float4*>(&sW1T[k * PW1 + c0 + 4]);
        ull ap[2] = {A.x, A.y};
        ull ws[8];
        PACK2(ws[0], wq0.x); PACK2(ws[1], wq0.y);
        PACK2(ws[2], wq0.z); PACK2(ws[3], wq0.w);
        PACK2(ws[4], wq1.x); PACK2(ws[5], wq1.y);
        PACK2(ws[6], wq1.z); PACK2(ws[7], wq1.w);
#pragma unroll
        for (int r = 0; r < 2; r++)
#pragma unroll
            for (int c = 0; c < 8; c++)
                FMA2(acc[r][c], ap[r], ws[c], acc[r][c]);
    }
    int n4 = node0 + rg * 4;
    if (n4 < NN) {
#pragma unroll
        for (int p = 0; p < 8; p++) {
            int col = c0 + p;
            float b = sB1[col];
            float l0, h0, l1, h1;
            UNPACK2(l0, h0, acc[0][p]);
            UNPACK2(l1, h1, acc[1][p]);
            float4 o = make_float4(fmaxf(l0 + b, 0.f), fmaxf(h0 + b, 0.f),
                                   fmaxf(l1 + b, 0.f), fmaxf(h1 + b, 0.f));
            *reinterpret_cast<float4*>(&g_hidT[(size_t)col * NN + n4]) = o;
        }
    }
}

// ---------- MLP stage C: hnT = hid @ W2^T + b2 ; 256 thr, 64 nodes ----------
#define C_SMEM_FLOATS (EMB2 * PW2 + 64 * PB + 64)
#define C_SMEM_BYTES (C_SMEM_FLOATS * 4)

__global__ __launch_bounds__(256, 4) void mlpC_kernel(
    const float* __restrict__ W2l, const float* __restrict__ b2l) {
    extern __shared__ float sm[];
    float* sW2T = sm;                  // [128 k][PW2] cols 0..63
    float* sHid = sW2T + EMB2 * PW2;   // [64 k][PB] (m contiguous)
    float* sB2 = sHid + 64 * PB;       // 64

    const int tid = threadIdx.x;
    const int node0 = blockIdx.x * 64;

    for (int idx = tid; idx < EMB * EMB2; idx += 256) {
        int j = idx >> 7, k = idx & 127;
        sW2T[k * PW2 + j] = W2l[idx];
    }
    if (tid < 64) sB2[tid] = b2l[tid];

    const int rg = tid & 15;         // rows rg*4 .. rg*4+3
    const int c0 = (tid >> 4) * 4;   // cols c0..c0+3
    ull acc[2][4];
#pragma unroll
    for (int r = 0; r < 2; r++)
#pragma unroll
        for (int c = 0; c < 4; c++) acc[r][c] = 0ull;

#pragma unroll
    for (int kh = 0; kh < 2; kh++) {
        __syncthreads();  // sW2T staged (kh=0) / prior sHid readers done (kh=1)
#pragma unroll
        for (int i = 0; i < 4; i++) {
            int idx = i * 256 + tid;
            int k = idx >> 4, q = idx & 15;
            int n4s = node0 + q * 4;
            float4 v = make_float4(0.f, 0.f, 0.f, 0.f);
            if (n4s < NN)
                v = *reinterpret_cast<const float4*>(
                    &g_hidT[(size_t)(kh * 64 + k) * NN + n4s]);
            *reinterpret_cast<float4*>(&sHid[k * PB + q * 4]) = v;
        }
        __syncthreads();
#pragma unroll 4
        for (int k = 0; k < 64; k++) {
            ulonglong2 A =
                *reinterpret_cast<const ulonglong2*>(&sHid[k * PB + rg * 4]);
            float4 wq = *reinterpret_cast<const float4*>(
                &sW2T[(kh * 64 + k) * PW2 + c0]);
            ull ap[2] = {A.x, A.y};
            ull ws[4];
            PACK2(ws[0], wq.x); PACK2(ws[1], wq.y);
            PACK2(ws[2], wq.z); PACK2(ws[3], wq.w);
#pragma unroll
            for (int r = 0; r < 2; r++)
#pragma unroll
                for (int c = 0; c < 4; c++)
                    FMA2(acc[r][c], ap[r], ws[c], acc[r][c]);
        }
    }
    int n4 = node0 + rg * 4;
    float st[4] = {0.f, 0.f, 0.f, 0.f};
    float sq[4] = {0.f, 0.f, 0.f, 0.f};
    if (n4 < NN) {
#pragma unroll
        for (int c = 0; c < 4; c++) {
            int col = c0 + c;
            float b = sB2[col];
            float l0, h0, l1, h1;
            UNPACK2(l0, h0, acc[0][c]);
            UNPACK2(l1, h1, acc[1][c]);
            l0 += b; h0 += b; l1 += b; h1 += b;
            *reinterpret_cast<float4*>(&g_hnT[(size_t)col * NN + n4]) =
                make_float4(l0, h0, l1, h1);
            st[c] = (l0 + h0) + (l1 + h1);
            sq[c] = l0 * l0 + h0 * h0 + l1 * l1 + h1 * h1;
        }
    }
    // reduce stats across the 16 row-groups (lanes differing in low 4 bits)
#pragma unroll
    for (int d = 1; d < 16; d <<= 1) {
#pragma unroll
        for (int c = 0; c < 4; c++) {
            st[c] += __shfl_xor_sync(0xffffffffu, st[c], d);
            sq[c] += __shfl_xor_sync(0xffffffffu, sq[c], d);
        }
    }
    if (rg == 0) {
#pragma unroll
        for (int c = 0; c < 4; c++) {
            atomicAdd(&g_stats[c0 + c], st[c]);
            atomicAdd(&g_stats[EMB + c0 + c], sq[c]);
        }
    }
}

// -------- normalize (+mish), transposed in, row-major out via smem tile -----
template <bool LAST>
__global__ __launch_bounds__(256) void norm_kernel(
    const float* __restrict__ gamma, const float* __restrict__ beta,
    float* __restrict__ outp) {
    __shared__ float sg[EMB], sb[EMB];
    __shared__ float sT[64 * 68];
    int tid = threadIdx.x;
    if (tid < EMB) {
        const float inv = 1.f / (float)NN;
        float mu = g_stats[tid] * inv;
        float var = g_stats[EMB + tid] * inv - mu * mu;
        float rs = rsqrtf(fmaxf(var, 0.f) + 1e-5f);
        float g = rs * gamma[tid];
        sg[tid] = g;
        sb[tid] = beta[tid] - mu * g;
    }
    __syncthreads();
    int node0 = blockIdx.x * 64;
#pragma unroll
    for (int it = 0; it < 4; it++) {
        int idx = it * 256 + tid;
        int ch = idx >> 4, m4 = (idx & 15) * 4;
        int n4 = node0 + m4;
        float4 v = make_float4(0.f, 0.f, 0.f, 0.f);
        if (n4 < NN)
            v = *reinterpret_cast<const float4*>(&g_hnT[(size_t)ch * NN + n4]);
        float vs[4] = {v.x, v.y, v.z, v.w};
        float gch = sg[ch], bch = sb[ch];
#pragma unroll
        for (int q = 0; q < 4; q++) {
            float y = fmaf(vs[q], gch, bch);
            if (!LAST) {
                float t = 1.f + __expf(y);
                y = y - __fdividef(2.f * y, fmaf(t, t, 1.f));
            }
            sT[(m4 + q) * 68 + ch] = y;
        }
    }
    __syncthreads();
    float* dst = LAST ? outp : g_h;
#pragma unroll
    for (int it = 0; it < 4; it++) {
        int idx = it * 256 + tid;
        int m = idx >> 4, c4 = (idx & 15) * 4;
        int n = node0 + m;
        if (n < NN) {
            float4 o = *reinterpret_cast<const float4*>(&sT[m * 68 + c4]);
            *reinterpret_cast<float4*>(&dst[(size_t)n * EMB + c4]) = o;
        }
    }
}

// ---------------- launch ----------------
extern "C" void kernel_launch(void* const* d_in, const int* in_sizes, int n_in,
                              void* d_out, int out_size) {
    const float* x = (const float*)d_in[0];
    const float* ea = (const float*)d_in[1];
    const float* Wemb = (const float*)d_in[2];
    const float* W1 = (const float*)d_in[3];
    const float* b1 = (const float*)d_in[4];
    const float* W2 = (const float*)d_in[5];
    const float* b2 = (const float*)d_in[6];
    const float* We = (const float*)d_in[7];
    const float* be = (const float*)d_in[8];
    const float* gamma = (const float*)d_in[9];
    const float* beta = (const float*)d_in[10];
    const int* ei = (const int*)d_in[11];
    float* out = (float*)d_out;

    cudaFuncSetAttribute(mlpB_kernel, cudaFuncAttributeMaxDynamicSharedMemorySize,
                         B_SMEM_BYTES);
    cudaFuncSetAttribute(mlpC_kernel, cudaFuncAttributeMaxDynamicSharedMemorySize,
                         C_SMEM_BYTES);

    void* cntp = nullptr;
    cudaGetSymbolAddress(&cntp, g_cnt);
    cudaMemsetAsync(cntp, 0, NN * sizeof(int));

    const int nblk = (NN + 63) / 64;   // 782 blocks — keep SMs fed

    hist_embed_kernel<<<(NE + 255) / 256, 256>>>(ei, x, Wemb);   // 0
    chunk_scan_kernel<<<NCHUNK, 1024>>>();                       // 1
    scan_apply_kernel<<<NCHUNK, 1024>>>();                       // 2
    // PROBE at launch index 3: mlpB on steady-state g_aggr (deterministic,
    // overwritten by the real pass) — keeps the MLP kernel under ncu.
    mlpB_kernel<<<nblk, 256, B_SMEM_BYTES>>>(W1, b1);            // 3 (profiled)
    fill_kernel<<<(NE + 255) / 256, 256>>>(ei);                  // 4
    sgather_kernel<<<(NN * 32 + 255) / 256, 256>>>(ea);          // 5

    for (int l = 0; l < NLAYER; l++) {
        gather_kernel<<<(NN * 32 + 255) / 256, 256>>>(
            We + (size_t)l * EMB * BOND_F, be + (size_t)l * EMB);
        mlpB_kernel<<<nblk, 256, B_SMEM_BYTES>>>(
            W1 + (size_t)l * EMB2 * EMB, b1 + (size_t)l * EMB2);
        mlpC_kernel<<<nblk, 256, C_SMEM_BYTES>>>(
            W2 + (size_t)l * EMB * EMB2, b2 + (size_t)l * EMB);
        if (l < NLAYER - 1)
            norm_kernel<false><<<nblk, 256>>>(
                gamma + (size_t)l * EMB, beta + (size_t)l * EMB, nullptr);
        else
            norm_kernel<true><<<nblk, 256>>>(
                gamma + (size_t)l * EMB, beta + (size_t)l * EMB, out);
    }
}

// round 13
// speedup vs baseline: 1.1550x; 1.0393x over previous
#include <cuda_runtime.h>
#include <math.h>

#define NLAYER 5
#define EMB 64
#define EMB2 128
#define ATOM_F 32
#define BOND_F 16
#define NN 50000
#define NE 800000
#define PW1 132
#define PW2 68
#define PB 68
#define NCHUNK 49   // ceil(NN/1024)

typedef unsigned long long ull;

// ---------------- scratch (static device globals; no runtime alloc) ----------
__device__ float g_h[NN * EMB];          // row-major [n][64]
__device__ float g_aggr[NN * EMB];       // row-major [n][64] (full GIN base)
__device__ float g_hidT[(size_t)EMB2 * NN];  // transposed [col][n]
__device__ float g_hnT[(size_t)EMB * NN];    // transposed [col][n]
__device__ float g_S[NN * BOND_F];
__device__ float g_stats[2 * EMB];
__device__ int   g_cnt[NN];
__device__ int   g_rowptr[NN + 1];
__device__ int   g_cur[NN];
__device__ int   g_blocksum[NCHUNK];
__device__ int   g_csr[NE];
__device__ int   g_src[NE];

// ---------------- f32x2 packed math ----------------
#define PACK2(d, x) asm("mov.b64 %0, {%1, %1};" : "=l"(d) : "r"(__float_as_uint(x)))
#define FMA2(d, a, b, c) asm("fma.rn.f32x2 %0, %1, %2, %3;" : "=l"(d) : "l"(a), "l"(b), "l"(c))
#define UNPACK2(lo, hi, v)                                            \
    {                                                                 \
        unsigned int u0_, u1_;                                        \
        asm("mov.b64 {%0, %1}, %2;" : "=r"(u0_), "=r"(u1_) : "l"(v)); \
        lo = __uint_as_float(u0_);                                    \
        hi = __uint_as_float(u1_);                                    \
    }

// -------- fused: histogram of dst + h = x @ Wemb^T ------
__global__ __launch_bounds__(256) void hist_embed_kernel(
    const int* __restrict__ ei, const float* __restrict__ x,
    const float* __restrict__ Wemb) {
    __shared__ float w[EMB * ATOM_F];
    int tid = threadIdx.x;
    for (int i = tid; i < EMB * ATOM_F; i += 256) w[i] = Wemb[i];
    __syncthreads();
    int gid = blockIdx.x * 256 + tid;
    if (gid < NE) atomicAdd(&g_cnt[ei[NE + gid]], 1);
    int node = gid >> 4;
    int j0 = (gid & 15) * 4;
    if (node < NN) {
        const float* xr = x + (size_t)node * ATOM_F;
        float a0 = 0.f, a1 = 0.f, a2 = 0.f, a3 = 0.f;
#pragma unroll
        for (int k = 0; k < ATOM_F; k++) {
            float xv = xr[k];
            a0 = fmaf(xv, w[(j0 + 0) * ATOM_F + k], a0);
            a1 = fmaf(xv, w[(j0 + 1) * ATOM_F + k], a1);
            a2 = fmaf(xv, w[(j0 + 2) * ATOM_F + k], a2);
            a3 = fmaf(xv, w[(j0 + 3) * ATOM_F + k], a3);
        }
        *reinterpret_cast<float4*>(&g_h[(size_t)node * EMB + j0]) =
            make_float4(a0, a1, a2, a3);
    }
}

// -------- parallel scan stage 1 --------
__global__ __launch_bounds__(1024) void chunk_scan_kernel() {
    __shared__ int warp_off[32];
    int tid = threadIdx.x;
    int lane = tid & 31, wid = tid >> 5;
    int i = blockIdx.x * 1024 + tid;
    int v = (i < NN) ? g_cnt[i] : 0;
    int x = v;
#pragma unroll
    for (int d = 1; d < 32; d <<= 1) {
        int y = __shfl_up_sync(0xffffffffu, x, d);
        if (lane >= d) x += y;
    }
    if (lane == 31) warp_off[wid] = x;
    __syncthreads();
    if (wid == 0) {
        int w = warp_off[lane];
        int xx = w;
#pragma unroll
        for (int d = 1; d < 32; d <<= 1) {
            int y = __shfl_up_sync(0xffffffffu, xx, d);
            if (lane >= d) xx += y;
        }
        warp_off[lane] = xx - w;
    }
    __syncthreads();
    int excl = warp_off[wid] + x - v;
    if (i < NN) g_rowptr[i] = excl;
    if (tid == 1023) g_blocksum[blockIdx.x] = excl + v;
}

// -------- parallel scan stage 2 --------
__global__ __launch_bounds__(1024) void scan_apply_kernel() {
    __shared__ int s_off;
    int tid = threadIdx.x;
    if (tid == 0) {
        int off = 0;
        for (int j = 0; j < (int)blockIdx.x; j++) off += g_blocksum[j];
        s_off = off;
        if (blockIdx.x == NCHUNK - 1)
            g_rowptr[NN] = off + g_blocksum[NCHUNK - 1];
    }
    __syncthreads();
    int i = blockIdx.x * 1024 + tid;
    if (i < NN) {
        int r = g_rowptr[i] + s_off;
        g_rowptr[i] = r;
        g_cur[i] = r;
    }
}

// ---------------- fill CSR buckets ----------------
__global__ void fill_kernel(const int* __restrict__ ei) {
    int e = blockIdx.x * blockDim.x + threadIdx.x;
    if (e >= NE) return;
    int dst = ei[NE + e];
    int pos = atomicAdd(&g_cur[dst], 1);
    g_csr[pos] = e;
    g_src[pos] = ei[e];
}

// ---------------- S[n] = sum of edge_attr over in-edges (once) ---------------
__global__ void sgather_kernel(const float* __restrict__ ea) {
    int gt = blockIdx.x * blockDim.x + threadIdx.x;
    int node = gt >> 5, lane = gt & 31;
    if (node >= NN) return;
    int beg = g_rowptr[node], end = g_rowptr[node + 1];
    float s = 0.f;
    for (int i = beg; i < end; i += 32) {
        int n = end - i;
        if (n > 32) n = 32;
        int eid = 0;
        if (lane < n) eid = g_csr[i + lane];
        for (int j = 0; j < n; j++) {
            int e = __shfl_sync(0xffffffffu, eid, j);
            if (lane < BOND_F) s += ea[(size_t)e * BOND_F + lane];
        }
    }
    if (lane < BOND_F) g_S[(size_t)node * BOND_F + lane] = s;
}

// ------- per layer: aggr[n] = h[n] + sum_{in} h[src] + deg*be + S@We^T -------
__global__ __launch_bounds__(256) void gather_kernel(
    const float* __restrict__ Wel, const float* __restrict__ bel) {
    __shared__ float sWeT[BOND_F * EMB];  // [k][j]
    __shared__ float sBe[EMB];
    int tid = threadIdx.x;
    for (int idx = tid; idx < BOND_F * EMB; idx += 256) {
        int k = idx >> 6, j = idx & 63;
        sWeT[idx] = Wel[j * BOND_F + k];
    }
    if (tid < EMB) sBe[tid] = bel[tid];
    if (blockIdx.x == 0 && tid < 2 * EMB) g_stats[tid] = 0.f;
    __syncthreads();

    int gt = blockIdx.x * 256 + tid;
    int node = gt >> 5, lane = gt & 31;
    if (node >= NN) return;
    const int half = lane >> 4, sub = lane & 15;
    int beg = g_rowptr[node], end = g_rowptr[node + 1];
    float4 acc0 = make_float4(0.f, 0.f, 0.f, 0.f);
    float4 acc1 = make_float4(0.f, 0.f, 0.f, 0.f);
    if (half == 0)
        acc0 = *reinterpret_cast<const float4*>(&g_h[(size_t)node * EMB + sub * 4]);
    for (int i = beg; i < end; i += 32) {
        int n = end - i;
        if (n > 32) n = 32;
        int src = 0;
        if (lane < n) src = g_src[i + lane];
        int j = 0;
        for (; j + 4 <= n; j += 4) {
            int s0 = __shfl_sync(0xffffffffu, src, j + half);
            int s1 = __shfl_sync(0xffffffffu, src, j + 2 + half);
            float4 v0 = __ldg(reinterpret_cast<const float4*>(
                &g_h[(size_t)s0 * EMB + sub * 4]));
            float4 v1 = __ldg(reinterpret_cast<const float4*>(
                &g_h[(size_t)s1 * EMB + sub * 4]));
            acc0.x += v0.x; acc0.y += v0.y; acc0.z += v0.z; acc0.w += v0.w;
            acc1.x += v1.x; acc1.y += v1.y; acc1.z += v1.z; acc1.w += v1.w;
        }
        if (j + 2 <= n) {
            int s0 = __shfl_sync(0xffffffffu, src, j + half);
            float4 v0 = __ldg(reinterpret_cast<const float4*>(
                &g_h[(size_t)s0 * EMB + sub * 4]));
            acc0.x += v0.x; acc0.y += v0.y; acc0.z += v0.z; acc0.w += v0.w;
            j += 2;
        }
        if (j < n) {
            int s0 = __shfl_sync(0xffffffffu, src, j);
            if (half == 0) {
                float4 v0 = __ldg(reinterpret_cast<const float4*>(
                    &g_h[(size_t)s0 * EMB + sub * 4]));
                acc0.x += v0.x; acc0.y += v0.y; acc0.z += v0.z; acc0.w += v0.w;
            }
        }
    }
    acc0.x += acc1.x; acc0.y += acc1.y; acc0.z += acc1.z; acc0.w += acc1.w;
    acc0.x += __shfl_xor_sync(0xffffffffu, acc0.x, 16);
    acc0.y += __shfl_xor_sync(0xffffffffu, acc0.y, 16);
    acc0.z += __shfl_xor_sync(0xffffffffu, acc0.z, 16);
    acc0.w += __shfl_xor_sync(0xffffffffu, acc0.w, 16);
    if (half == 0) {
        float deg = (float)(end - beg + 1);
        const float4* sp =
            reinterpret_cast<const float4*>(&g_S[(size_t)node * BOND_F]);
        float4 s0 = sp[0], s1 = sp[1], s2 = sp[2], s3 = sp[3];
        float se[16] = {s0.x, s0.y, s0.z, s0.w, s1.x, s1.y, s1.z, s1.w,
                        s2.x, s2.y, s2.z, s2.w, s3.x, s3.y, s3.z, s3.w};
        float4 be4 = *reinterpret_cast<const float4*>(&sBe[sub * 4]);
        float4 ee;
        ee.x = deg * be4.x; ee.y = deg * be4.y;
        ee.z = deg * be4.z; ee.w = deg * be4.w;
#pragma unroll
        for (int k = 0; k < BOND_F; k++) {
            float4 w4 = *reinterpret_cast<const float4*>(&sWeT[k * EMB + sub * 4]);
            ee.x = fmaf(se[k], w4.x, ee.x);
            ee.y = fmaf(se[k], w4.y, ee.y);
            ee.z = fmaf(se[k], w4.z, ee.z);
            ee.w = fmaf(se[k], w4.w, ee.w);
        }
        acc0.x += ee.x; acc0.y += ee.y; acc0.z += ee.z; acc0.w += ee.w;
        *reinterpret_cast<float4*>(&g_aggr[(size_t)node * EMB + sub * 4]) = acc0;
    }
}

// ---------- MLP stage B: hidT = relu(base @ W1^T + b1); 256 thr, 64 nodes ----
#define B_SMEM_FLOATS (64 * PW1 + 64 * PB + 128)
#define B_SMEM_BYTES (B_SMEM_FLOATS * 4)

__global__ __launch_bounds__(256, 4) void mlpB_kernel(
    const float* __restrict__ W1l, const float* __restrict__ b1l) {
    extern __shared__ float sm[];
    float* sW1T = sm;                 // [64 k][PW1] cols 0..127
    float* sBase = sW1T + 64 * PW1;   // [64 k][PB] (m contiguous)
    float* sB1 = sBase + 64 * PB;     // 128

    const int tid = threadIdx.x;
    const int node0 = blockIdx.x * 64;

    for (int idx = tid; idx < EMB2 * EMB; idx += 256) {
        int i = idx >> 6, k = idx & 63;
        sW1T[k * PW1 + i] = W1l[idx];
    }
    if (tid < 128) sB1[tid] = b1l[tid];
#pragma unroll
    for (int i = 0; i < 4; i++) {
        int idx = i * 256 + tid;
        int m = idx & 63, q = idx >> 6;  // q 0..15
        int n = node0 + m;
        float4 v = make_float4(0.f, 0.f, 0.f, 0.f);
        if (n < NN)
            v = *reinterpret_cast<const float4*>(&g_aggr[(size_t)n * EMB + q * 4]);
        sBase[(4 * q + 0) * PB + m] = v.x;
        sBase[(4 * q + 1) * PB + m] = v.y;
        sBase[(4 * q + 2) * PB + m] = v.z;
        sBase[(4 * q + 3) * PB + m] = v.w;
    }
    __syncthreads();

    const int rg = tid & 15;         // rows rg*4 .. rg*4+3
    const int c0 = (tid >> 4) * 8;   // cols c0..c0+7
    ull acc[2][8];
#pragma unroll
    for (int r = 0; r < 2; r++)
#pragma unroll
        for (int c = 0; c < 8; c++) acc[r][c] = 0ull;
#pragma unroll 4
    for (int k = 0; k < EMB; k++) {
        ulonglong2 A = *reinterpret_cast<const ulonglong2*>(&sBase[k * PB + rg * 4]);
        ull ap0 = A.x, ap1 = A.y;
        // column half 0 — only 4 packed weights live at a time
        {
            float4 wq = *reinterpret_cast<const float4*>(&sW1T[k * PW1 + c0]);
            ull w0, w1, w2, w3;
            PACK2(w0, wq.x); PACK2(w1, wq.y); PACK2(w2, wq.z); PACK2(w3, wq.w);
            FMA2(acc[0][0], ap0, w0, acc[0][0]); FMA2(acc[1][0], ap1, w0, acc[1][0]);
            FMA2(acc[0][1], ap0, w1, acc[0][1]); FMA2(acc[1][1], ap1, w1, acc[1][1]);
            FMA2(acc[0][2], ap0, w2, acc[0][2]); FMA2(acc[1][2], ap1, w2, acc[1][2]);
            FMA2(acc[0][3], ap0, w3, acc[0][3]); FMA2(acc[1][3], ap1, w3, acc[1][3]);
        }
        // column half 1
        {
            float4 wq = *reinterpret_cast<const float4*>(&sW1T[k * PW1 + c0 + 4]);
            ull w0, w1, w2, w3;
            PACK2(w0, wq.x); PACK2(w1, wq.y); PACK2(w2, wq.z); PACK2(w3, wq.w);
            FMA2(acc[0][4], ap0, w0, acc[0][4]); FMA2(acc[1][4], ap1, w0, acc[1][4]);
            FMA2(acc[0][5], ap0, w1, acc[0][5]); FMA2(acc[1][5], ap1, w1, acc[1][5]);
            FMA2(acc[0][6], ap0, w2, acc[0][6]); FMA2(acc[1][6], ap1, w2, acc[1][6]);
            FMA2(acc[0][7], ap0, w3, acc[0][7]); FMA2(acc[1][7], ap1, w3, acc[1][7]);
        }
    }
    int n4 = node0 + rg * 4;
    if (n4 < NN) {
#pragma unroll
        for (int p = 0; p < 8; p++) {
            int col = c0 + p;
            float b = sB1[col];
            float l0, h0, l1, h1;
            UNPACK2(l0, h0, acc[0][p]);
            UNPACK2(l1, h1, acc[1][p]);
            float4 o = make_float4(fmaxf(l0 + b, 0.f), fmaxf(h0 + b, 0.f),
                                   fmaxf(l1 + b, 0.f), fmaxf(h1 + b, 0.f));
            *reinterpret_cast<float4*>(&g_hidT[(size_t)col * NN + n4]) = o;
        }
    }
}

// ---------- MLP stage C: hnT = hid @ W2^T + b2 ; 256 thr, 64 nodes ----------
#define C_SMEM_FLOATS (EMB2 * PW2 + 64 * PB + 64)
#define C_SMEM_BYTES (C_SMEM_FLOATS * 4)

__global__ __launch_bounds__(256, 4) void mlpC_kernel(
    const float* __restrict__ W2l, const float* __restrict__ b2l) {
    extern __shared__ float sm[];
    float* sW2T = sm;                  // [128 k][PW2] cols 0..63
    float* sHid = sW2T + EMB2 * PW2;   // [64 k][PB] (m contiguous)
    float* sB2 = sHid + 64 * PB;       // 64

    const int tid = threadIdx.x;
    const int node0 = blockIdx.x * 64;

    for (int idx = tid; idx < EMB * EMB2; idx += 256) {
        int j = idx >> 7, k = idx & 127;
        sW2T[k * PW2 + j] = W2l[idx];
    }
    if (tid < 64) sB2[tid] = b2l[tid];

    const int rg = tid & 15;         // rows rg*4 .. rg*4+3
    const int c0 = (tid >> 4) * 4;   // cols c0..c0+3
    ull acc[2][4];
#pragma unroll
    for (int r = 0; r < 2; r++)
#pragma unroll
        for (int c = 0; c < 4; c++) acc[r][c] = 0ull;

#pragma unroll
    for (int kh = 0; kh < 2; kh++) {
        __syncthreads();  // sW2T staged (kh=0) / prior sHid readers done (kh=1)
#pragma unroll
        for (int i = 0; i < 4; i++) {
            int idx = i * 256 + tid;
            int k = idx >> 4, q = idx & 15;
            int n4s = node0 + q * 4;
            float4 v = make_float4(0.f, 0.f, 0.f, 0.f);
            if (n4s < NN)
                v = *reinterpret_cast<const float4*>(
                    &g_hidT[(size_t)(kh * 64 + k) * NN + n4s]);
            *reinterpret_cast<float4*>(&sHid[k * PB + q * 4]) = v;
        }
        __syncthreads();
#pragma unroll 4
        for (int k = 0; k < 64; k++) {
            ulonglong2 A =
                *reinterpret_cast<const ulonglong2*>(&sHid[k * PB + rg * 4]);
            ull ap0 = A.x, ap1 = A.y;
            float4 wq = *reinterpret_cast<const float4*>(
                &sW2T[(kh * 64 + k) * PW2 + c0]);
            ull w0, w1, w2, w3;
            PACK2(w0, wq.x); PACK2(w1, wq.y); PACK2(w2, wq.z); PACK2(w3, wq.w);
            FMA2(acc[0][0], ap0, w0, acc[0][0]); FMA2(acc[1][0], ap1, w0, acc[1][0]);
            FMA2(acc[0][1], ap0, w1, acc[0][1]); FMA2(acc[1][1], ap1, w1, acc[1][1]);
            FMA2(acc[0][2], ap0, w2, acc[0][2]); FMA2(acc[1][2], ap1, w2, acc[1][2]);
            FMA2(acc[0][3], ap0, w3, acc[0][3]); FMA2(acc[1][3], ap1, w3, acc[1][3]);
        }
    }
    int n4 = node0 + rg * 4;
    float st[4] = {0.f, 0.f, 0.f, 0.f};
    float sq[4] = {0.f, 0.f, 0.f, 0.f};
    if (n4 < NN) {
#pragma unroll
        for (int c = 0; c < 4; c++) {
            int col = c0 + c;
            float b = sB2[col];
            float l0, h0, l1, h1;
            UNPACK2(l0, h0, acc[0][c]);
            UNPACK2(l1, h1, acc[1][c]);
            l0 += b; h0 += b; l1 += b; h1 += b;
            *reinterpret_cast<float4*>(&g_hnT[(size_t)col * NN + n4]) =
                make_float4(l0, h0, l1, h1);
            st[c] = (l0 + h0) + (l1 + h1);
            sq[c] = l0 * l0 + h0 * h0 + l1 * l1 + h1 * h1;
        }
    }
    // reduce stats across the 16 row-groups (lanes differing in low 4 bits)
#pragma unroll
    for (int d = 1; d < 16; d <<= 1) {
#pragma unroll
        for (int c = 0; c < 4; c++) {
            st[c] += __shfl_xor_sync(0xffffffffu, st[c], d);
            sq[c] += __shfl_xor_sync(0xffffffffu, sq[c], d);
        }
    }
    if (rg == 0) {
#pragma unroll
        for (int c = 0; c < 4; c++) {
            atomicAdd(&g_stats[c0 + c], st[c]);
            atomicAdd(&g_stats[EMB + c0 + c], sq[c]);
        }
    }
}

// -------- normalize (+mish), transposed in, row-major out via smem tile -----
template <bool LAST>
__global__ __launch_bounds__(256) void norm_kernel(
    const float* __restrict__ gamma, const float* __restrict__ beta,
    float* __restrict__ outp) {
    __shared__ float sg[EMB], sb[EMB];
    __shared__ float sT[64 * 68];
    int tid = threadIdx.x;
    if (tid < EMB) {
        const float inv = 1.f / (float)NN;
        float mu = g_stats[tid] * inv;
        float var = g_stats[EMB + tid] * inv - mu * mu;
        float rs = rsqrtf(fmaxf(var, 0.f) + 1e-5f);
        float g = rs * gamma[tid];
        sg[tid] = g;
        sb[tid] = beta[tid] - mu * g;
    }
    __syncthreads();
    int node0 = blockIdx.x * 64;
#pragma unroll
    for (int it = 0; it < 4; it++) {
        int idx = it * 256 + tid;
        int ch = idx >> 4, m4 = (idx & 15) * 4;
        int n4 = node0 + m4;
        float4 v = make_float4(0.f, 0.f, 0.f, 0.f);
        if (n4 < NN)
            v = *reinterpret_cast<const float4*>(&g_hnT[(size_t)ch * NN + n4]);
        float vs[4] = {v.x, v.y, v.z, v.w};
        float gch = sg[ch], bch = sb[ch];
#pragma unroll
        for (int q = 0; q < 4; q++) {
            float y = fmaf(vs[q], gch, bch);
            if (!LAST) {
                float t = 1.f + __expf(y);
                y = y - __fdividef(2.f * y, fmaf(t, t, 1.f));
            }
            sT[(m4 + q) * 68 + ch] = y;
        }
    }
    __syncthreads();
    float* dst = LAST ? outp : g_h;
#pragma unroll
    for (int it = 0; it < 4; it++) {
        int idx = it * 256 + tid;
        int m = idx >> 4, c4 = (idx & 15) * 4;
        int n = node0 + m;
        if (n < NN) {
            float4 o = *reinterpret_cast<const float4*>(&sT[m * 68 + c4]);
            *reinterpret_cast<float4*>(&dst[(size_t)n * EMB + c4]) = o;
        }
    }
}

// ---------------- launch ----------------
extern "C" void kernel_launch(void* const* d_in, const int* in_sizes, int n_in,
                              void* d_out, int out_size) {
    const float* x = (const float*)d_in[0];
    const float* ea = (const float*)d_in[1];
    const float* Wemb = (const float*)d_in[2];
    const float* W1 = (const float*)d_in[3];
    const float* b1 = (const float*)d_in[4];
    const float* W2 = (const float*)d_in[5];
    const float* b2 = (const float*)d_in[6];
    const float* We = (const float*)d_in[7];
    const float* be = (const float*)d_in[8];
    const float* gamma = (const float*)d_in[9];
    const float* beta = (const float*)d_in[10];
    const int* ei = (const int*)d_in[11];
    float* out = (float*)d_out;

    cudaFuncSetAttribute(mlpB_kernel, cudaFuncAttributeMaxDynamicSharedMemorySize,
                         B_SMEM_BYTES);
    cudaFuncSetAttribute(mlpC_kernel, cudaFuncAttributeMaxDynamicSharedMemorySize,
                         C_SMEM_BYTES);

    void* cntp = nullptr;
    cudaGetSymbolAddress(&cntp, g_cnt);
    cudaMemsetAsync(cntp, 0, NN * sizeof(int));

    const int nblk = (NN + 63) / 64;   // 782 blocks

    hist_embed_kernel<<<(NE + 255) / 256, 256>>>(ei, x, Wemb);   // 0
    chunk_scan_kernel<<<NCHUNK, 1024>>>();                       // 1
    scan_apply_kernel<<<NCHUNK, 1024>>>();                       // 2
    fill_kernel<<<(NE + 255) / 256, 256>>>(ei);                  // 3 (profiled)
    sgather_kernel<<<(NN * 32 + 255) / 256, 256>>>(ea);          // 4

    for (int l = 0; l < NLAYER; l++) {
        gather_kernel<<<(NN * 32 + 255) / 256, 256>>>(
            We + (size_t)l * EMB * BOND_F, be + (size_t)l * EMB);
        mlpB_kernel<<<nblk, 256, B_SMEM_BYTES>>>(
            W1 + (size_t)l * EMB2 * EMB, b1 + (size_t)l * EMB2);
        mlpC_kernel<<<nblk, 256, C_SMEM_BYTES>>>(
            W2 + (size_t)l * EMB * EMB2, b2 + (size_t)l * EMB);
        if (l < NLAYER - 1)
            norm_kernel<false><<<nblk, 256>>>(
                gamma + (size_t)l * EMB, beta + (size_t)l * EMB, nullptr);
        else
            norm_kernel<true><<<nblk, 256>>>(
                gamma + (size_t)l * EMB, beta + (size_t)l * EMB, out);
    }
}

// round 14
// speedup vs baseline: 1.2228x; 1.0587x over previous
#include <cuda_runtime.h>
#include <math.h>

#define NLAYER 5
#define EMB 64
#define EMB2 128
#define ATOM_F 32
#define BOND_F 16
#define NN 50000
#define NE 800000
#define PW1 132
#define PH 68
#define PB 68
#define NCHUNK 49   // ceil(NN/1024)

typedef unsigned long long ull;

// ---------------- scratch (static device globals; no runtime alloc) ----------
__device__ float g_h[NN * EMB];          // row-major [n][64]
__device__ float g_aggr[NN * EMB];       // row-major [n][64] (full GIN base)
__device__ float g_hnT[(size_t)EMB * NN];    // transposed [col][n]
__device__ float g_S[NN * BOND_F];
__device__ float g_stats[2 * EMB];
__device__ int   g_cnt[NN];
__device__ int   g_rowptr[NN + 1];
__device__ int   g_cur[NN];
__device__ int   g_blocksum[NCHUNK];
__device__ int   g_csr[NE];
__device__ int   g_src[NE];

// ---------------- f32x2 packed math ----------------
#define PACK2(d, x) asm("mov.b64 %0, {%1, %1};" : "=l"(d) : "r"(__float_as_uint(x)))
#define FMA2(d, a, b, c) asm("fma.rn.f32x2 %0, %1, %2, %3;" : "=l"(d) : "l"(a), "l"(b), "l"(c))
#define UNPACK2(lo, hi, v)                                            \
    {                                                                 \
        unsigned int u0_, u1_;                                        \
        asm("mov.b64 {%0, %1}, %2;" : "=r"(u0_), "=r"(u1_) : "l"(v)); \
        lo = __uint_as_float(u0_);                                    \
        hi = __uint_as_float(u1_);                                    \
    }

// -------- fused: histogram of dst + h = x @ Wemb^T ------
__global__ __launch_bounds__(256) void hist_embed_kernel(
    const int* __restrict__ ei, const float* __restrict__ x,
    const float* __restrict__ Wemb) {
    __shared__ float w[EMB * ATOM_F];
    int tid = threadIdx.x;
    for (int i = tid; i < EMB * ATOM_F; i += 256) w[i] = Wemb[i];
    __syncthreads();
    int gid = blockIdx.x * 256 + tid;
    if (gid < NE) atomicAdd(&g_cnt[ei[NE + gid]], 1);
    int node = gid >> 4;
    int j0 = (gid & 15) * 4;
    if (node < NN) {
        const float* xr = x + (size_t)node * ATOM_F;
        float a0 = 0.f, a1 = 0.f, a2 = 0.f, a3 = 0.f;
#pragma unroll
        for (int k = 0; k < ATOM_F; k++) {
            float xv = xr[k];
            a0 = fmaf(xv, w[(j0 + 0) * ATOM_F + k], a0);
            a1 = fmaf(xv, w[(j0 + 1) * ATOM_F + k], a1);
            a2 = fmaf(xv, w[(j0 + 2) * ATOM_F + k], a2);
            a3 = fmaf(xv, w[(j0 + 3) * ATOM_F + k], a3);
        }
        *reinterpret_cast<float4*>(&g_h[(size_t)node * EMB + j0]) =
            make_float4(a0, a1, a2, a3);
    }
}

// -------- parallel scan stage 1 --------
__global__ __launch_bounds__(1024) void chunk_scan_kernel() {
    __shared__ int warp_off[32];
    int tid = threadIdx.x;
    int lane = tid & 31, wid = tid >> 5;
    int i = blockIdx.x * 1024 + tid;
    int v = (i < NN) ? g_cnt[i] : 0;
    int x = v;
#pragma unroll
    for (int d = 1; d < 32; d <<= 1) {
        int y = __shfl_up_sync(0xffffffffu, x, d);
        if (lane >= d) x += y;
    }
    if (lane == 31) warp_off[wid] = x;
    __syncthreads();
    if (wid == 0) {
        int w = warp_off[lane];
        int xx = w;
#pragma unroll
        for (int d = 1; d < 32; d <<= 1) {
            int y = __shfl_up_sync(0xffffffffu, xx, d);
            if (lane >= d) xx += y;
        }
        warp_off[lane] = xx - w;
    }
    __syncthreads();
    int excl = warp_off[wid] + x - v;
    if (i < NN) g_rowptr[i] = excl;
    if (tid == 1023) g_blocksum[blockIdx.x] = excl + v;
}

// -------- parallel scan stage 2 --------
__global__ __launch_bounds__(1024) void scan_apply_kernel() {
    __shared__ int s_off;
    int tid = threadIdx.x;
    if (tid == 0) {
        int off = 0;
        for (int j = 0; j < (int)blockIdx.x; j++) off += g_blocksum[j];
        s_off = off;
        if (blockIdx.x == NCHUNK - 1)
            g_rowptr[NN] = off + g_blocksum[NCHUNK - 1];
    }
    __syncthreads();
    int i = blockIdx.x * 1024 + tid;
    if (i < NN) {
        int r = g_rowptr[i] + s_off;
        g_rowptr[i] = r;
        g_cur[i] = r;
    }
}

// ---------------- fill CSR buckets ----------------
__global__ void fill_kernel(const int* __restrict__ ei) {
    int e = blockIdx.x * blockDim.x + threadIdx.x;
    if (e >= NE) return;
    int dst = ei[NE + e];
    int pos = atomicAdd(&g_cur[dst], 1);
    g_csr[pos] = e;
    g_src[pos] = ei[e];
}

// ---------------- S[n] = sum of edge_attr over in-edges (once) ---------------
__global__ void sgather_kernel(const float* __restrict__ ea) {
    int gt = blockIdx.x * blockDim.x + threadIdx.x;
    int node = gt >> 5, lane = gt & 31;
    if (node >= NN) return;
    int beg = g_rowptr[node], end = g_rowptr[node + 1];
    float s = 0.f;
    for (int i = beg; i < end; i += 32) {
        int n = end - i;
        if (n > 32) n = 32;
        int eid = 0;
        if (lane < n) eid = g_csr[i + lane];
        for (int j = 0; j < n; j++) {
            int e = __shfl_sync(0xffffffffu, eid, j);
            if (lane < BOND_F) s += ea[(size_t)e * BOND_F + lane];
        }
    }
    if (lane < BOND_F) g_S[(size_t)node * BOND_F + lane] = s;
}

// ------- per layer: aggr[n] = h[n] + sum_{in} h[src] + deg*be + S@We^T -------
__global__ __launch_bounds__(256) void gather_kernel(
    const float* __restrict__ Wel, const float* __restrict__ bel) {
    __shared__ float sWeT[BOND_F * EMB];  // [k][j]
    __shared__ float sBe[EMB];
    int tid = threadIdx.x;
    for (int idx = tid; idx < BOND_F * EMB; idx += 256) {
        int k = idx >> 6, j = idx & 63;
        sWeT[idx] = Wel[j * BOND_F + k];
    }
    if (tid < EMB) sBe[tid] = bel[tid];
    if (blockIdx.x == 0 && tid < 2 * EMB) g_stats[tid] = 0.f;
    __syncthreads();

    int gt = blockIdx.x * 256 + tid;
    int node = gt >> 5, lane = gt & 31;
    if (node >= NN) return;
    const int half = lane >> 4, sub = lane & 15;
    int beg = g_rowptr[node], end = g_rowptr[node + 1];
    float4 acc0 = make_float4(0.f, 0.f, 0.f, 0.f);
    float4 acc1 = make_float4(0.f, 0.f, 0.f, 0.f);
    if (half == 0)
        acc0 = *reinterpret_cast<const float4*>(&g_h[(size_t)node * EMB + sub * 4]);
    for (int i = beg; i < end; i += 32) {
        int n = end - i;
        if (n > 32) n = 32;
        int src = 0;
        if (lane < n) src = g_src[i + lane];
        int j = 0;
        for (; j + 4 <= n; j += 4) {
            int s0 = __shfl_sync(0xffffffffu, src, j + half);
            int s1 = __shfl_sync(0xffffffffu, src, j + 2 + half);
            float4 v0 = __ldg(reinterpret_cast<const float4*>(
                &g_h[(size_t)s0 * EMB + sub * 4]));
            float4 v1 = __ldg(reinterpret_cast<const float4*>(
                &g_h[(size_t)s1 * EMB + sub * 4]));
            acc0.x += v0.x; acc0.y += v0.y; acc0.z += v0.z; acc0.w += v0.w;
            acc1.x += v1.x; acc1.y += v1.y; acc1.z += v1.z; acc1.w += v1.w;
        }
        if (j + 2 <= n) {
            int s0 = __shfl_sync(0xffffffffu, src, j + half);
            float4 v0 = __ldg(reinterpret_cast<const float4*>(
                &g_h[(size_t)s0 * EMB + sub * 4]));
            acc0.x += v0.x; acc0.y += v0.y; acc0.z += v0.z; acc0.w += v0.w;
            j += 2;
        }
        if (j < n) {
            int s0 = __shfl_sync(0xffffffffu, src, j);
            if (half == 0) {
                float4 v0 = __ldg(reinterpret_cast<const float4*>(
                    &g_h[(size_t)s0 * EMB + sub * 4]));
                acc0.x += v0.x; acc0.y += v0.y; acc0.z += v0.z; acc0.w += v0.w;
            }
        }
    }
    acc0.x += acc1.x; acc0.y += acc1.y; acc0.z += acc1.z; acc0.w += acc1.w;
    acc0.x += __shfl_xor_sync(0xffffffffu, acc0.x, 16);
    acc0.y += __shfl_xor_sync(0xffffffffu, acc0.y, 16);
    acc0.z += __shfl_xor_sync(0xffffffffu, acc0.z, 16);
    acc0.w += __shfl_xor_sync(0xffffffffu, acc0.w, 16);
    if (half == 0) {
        float deg = (float)(end - beg + 1);
        const float4* sp =
            reinterpret_cast<const float4*>(&g_S[(size_t)node * BOND_F]);
        float4 s0 = sp[0], s1 = sp[1], s2 = sp[2], s3 = sp[3];
        float se[16] = {s0.x, s0.y, s0.z, s0.w, s1.x, s1.y, s1.z, s1.w,
                        s2.x, s2.y, s2.z, s2.w, s3.x, s3.y, s3.z, s3.w};
        float4 be4 = *reinterpret_cast<const float4*>(&sBe[sub * 4]);
        float4 ee;
        ee.x = deg * be4.x; ee.y = deg * be4.y;
        ee.z = deg * be4.z; ee.w = deg * be4.w;
#pragma unroll
        for (int k = 0; k < BOND_F; k++) {
            float4 w4 = *reinterpret_cast<const float4*>(&sWeT[k * EMB + sub * 4]);
            ee.x = fmaf(se[k], w4.x, ee.x);
            ee.y = fmaf(se[k], w4.y, ee.y);
            ee.z = fmaf(se[k], w4.z, ee.z);
            ee.w = fmaf(se[k], w4.w, ee.w);
        }
        acc0.x += ee.x; acc0.y += ee.y; acc0.z += ee.z; acc0.w += ee.w;
        *reinterpret_cast<float4*>(&g_aggr[(size_t)node * EMB + sub * 4]) = acc0;
    }
}

// ---------- fused MLP: hn = (relu(base@W1^T+b1))@W2^T + b2 ; BN stats -------
// Region0 (8704 floats): phase1 sW1T [64][PW1], phase2 sHid [128][PH]
// Region1 (4352 floats): phase1 sBase [64][PB], phase2 sW2T half [64][PH]
#define F_SMEM_FLOATS (8704 + 4352 + 128 + 64)
#define F_SMEM_BYTES (F_SMEM_FLOATS * 4)

__global__ __launch_bounds__(256, 4) void mlp_fused_kernel(
    const float* __restrict__ W1l, const float* __restrict__ b1l,
    const float* __restrict__ W2l, const float* __restrict__ b2l) {
    extern __shared__ float sm[];
    float* region0 = sm;              // 8704 floats
    float* region1 = sm + 8704;       // 4352 floats
    float* sB1 = sm + 8704 + 4352;    // 128
    float* sB2 = sB1 + 128;           // 64

    float* sW1T = region0;            // [64 k][PW1] cols 0..127 (phase 1)
    float* sHid = region0;            // [128 col][PH] (phase 2)
    float* sBase = region1;           // [64 k][PB]  (phase 1)
    float* sW2T = region1;            // [64 kk][PH] cols 0..63 (phase 2, halves)

    const int tid = threadIdx.x;
    const int node0 = blockIdx.x * 64;

    // ---- phase 1 staging ----
    for (int idx = tid; idx < EMB2 * EMB; idx += 256) {
        int i = idx >> 6, k = idx & 63;
        sW1T[k * PW1 + i] = W1l[idx];
    }
    if (tid < 128) sB1[tid] = b1l[tid];
    if (tid < 64) sB2[tid] = b2l[tid];
#pragma unroll
    for (int i = 0; i < 4; i++) {
        int idx = i * 256 + tid;
        int m = idx & 63, q = idx >> 6;  // q 0..15
        int n = node0 + m;
        float4 v = make_float4(0.f, 0.f, 0.f, 0.f);
        if (n < NN)
            v = *reinterpret_cast<const float4*>(&g_aggr[(size_t)n * EMB + q * 4]);
        sBase[(4 * q + 0) * PB + m] = v.x;
        sBase[(4 * q + 1) * PB + m] = v.y;
        sBase[(4 * q + 2) * PB + m] = v.z;
        sBase[(4 * q + 3) * PB + m] = v.w;
    }
    __syncthreads();

    const int rg = tid & 15;          // rows rg*4 .. rg*4+3
    const int c0 = (tid >> 4) * 8;    // GEMM1 cols c0..c0+7
    const int c20 = (tid >> 4) * 4;   // GEMM2 cols c20..c20+3

    // ---- GEMM1: acc[2][8] over k=0..63 ----
    ull acc[2][8];
#pragma unroll
    for (int r = 0; r < 2; r++)
#pragma unroll
        for (int c = 0; c < 8; c++) acc[r][c] = 0ull;
#pragma unroll 4
    for (int k = 0; k < EMB; k++) {
        ulonglong2 A = *reinterpret_cast<const ulonglong2*>(&sBase[k * PB + rg * 4]);
        ull ap0 = A.x, ap1 = A.y;
        {
            float4 wq = *reinterpret_cast<const float4*>(&sW1T[k * PW1 + c0]);
            ull w0, w1, w2, w3;
            PACK2(w0, wq.x); PACK2(w1, wq.y); PACK2(w2, wq.z); PACK2(w3, wq.w);
            FMA2(acc[0][0], ap0, w0, acc[0][0]); FMA2(acc[1][0], ap1, w0, acc[1][0]);
            FMA2(acc[0][1], ap0, w1, acc[0][1]); FMA2(acc[1][1], ap1, w1, acc[1][1]);
            FMA2(acc[0][2], ap0, w2, acc[0][2]); FMA2(acc[1][2], ap1, w2, acc[1][2]);
            FMA2(acc[0][3], ap0, w3, acc[0][3]); FMA2(acc[1][3], ap1, w3, acc[1][3]);
        }
        {
            float4 wq = *reinterpret_cast<const float4*>(&sW1T[k * PW1 + c0 + 4]);
            ull w0, w1, w2, w3;
            PACK2(w0, wq.x); PACK2(w1, wq.y); PACK2(w2, wq.z); PACK2(w3, wq.w);
            FMA2(acc[0][4], ap0, w0, acc[0][4]); FMA2(acc[1][4], ap1, w0, acc[1][4]);
            FMA2(acc[0][5], ap0, w1, acc[0][5]); FMA2(acc[1][5], ap1, w1, acc[1][5]);
            FMA2(acc[0][6], ap0, w2, acc[0][6]); FMA2(acc[1][6], ap1, w2, acc[1][6]);
            FMA2(acc[0][7], ap0, w3, acc[0][7]); FMA2(acc[1][7], ap1, w3, acc[1][7]);
        }
    }
    __syncthreads();   // all reads of sW1T/sBase done — regions reusable

    // ---- hid = relu(acc + b1) into sHid[col][m] (region0) ----
#pragma unroll
    for (int p = 0; p < 8; p++) {
        int col = c0 + p;
        float b = sB1[col];
        float l0, h0, l1, h1;
        UNPACK2(l0, h0, acc[0][p]);
        UNPACK2(l1, h1, acc[1][p]);
        float4 o = make_float4(fmaxf(l0 + b, 0.f), fmaxf(h0 + b, 0.f),
                               fmaxf(l1 + b, 0.f), fmaxf(h1 + b, 0.f));
        *reinterpret_cast<float4*>(&sHid[col * PH + rg * 4]) = o;
    }

    // ---- GEMM2 in two k-halves, W2 staged into region1 ----
    ull acc2[2][4];
#pragma unroll
    for (int r = 0; r < 2; r++)
#pragma unroll
        for (int c = 0; c < 4; c++) acc2[r][c] = 0ull;

#pragma unroll
    for (int kh = 0; kh < 2; kh++) {
        __syncthreads();  // hid writes done (kh=0) / prior W2 half reads done
        for (int idx = tid; idx < 64 * 64; idx += 256) {
            int j = idx >> 6, kk = idx & 63;
            sW2T[kk * PH + j] = W2l[j * EMB2 + kh * 64 + kk];
        }
        __syncthreads();
#pragma unroll 4
        for (int k = 0; k < 64; k++) {
            ulonglong2 A = *reinterpret_cast<const ulonglong2*>(
                &sHid[(kh * 64 + k) * PH + rg * 4]);
            ull ap0 = A.x, ap1 = A.y;
            float4 wq = *reinterpret_cast<const float4*>(&sW2T[k * PH + c20]);
            ull w0, w1, w2, w3;
            PACK2(w0, wq.x); PACK2(w1, wq.y); PACK2(w2, wq.z); PACK2(w3, wq.w);
            FMA2(acc2[0][0], ap0, w0, acc2[0][0]); FMA2(acc2[1][0], ap1, w0, acc2[1][0]);
            FMA2(acc2[0][1], ap0, w1, acc2[0][1]); FMA2(acc2[1][1], ap1, w1, acc2[1][1]);
            FMA2(acc2[0][2], ap0, w2, acc2[0][2]); FMA2(acc2[1][2], ap1, w2, acc2[1][2]);
            FMA2(acc2[0][3], ap0, w3, acc2[0][3]); FMA2(acc2[1][3], ap1, w3, acc2[1][3]);
        }
    }

    // ---- epilogue: hnT + BN partial stats ----
    int n4 = node0 + rg * 4;
    float st[4] = {0.f, 0.f, 0.f, 0.f};
    float sq[4] = {0.f, 0.f, 0.f, 0.f};
    if (n4 < NN) {
#pragma unroll
        for (int c = 0; c < 4; c++) {
            int col = c20 + c;
            float b = sB2[col];
            float l0, h0, l1, h1;
            UNPACK2(l0, h0, acc2[0][c]);
            UNPACK2(l1, h1, acc2[1][c]);
            l0 += b; h0 += b; l1 += b; h1 += b;
            *reinterpret_cast<float4*>(&g_hnT[(size_t)col * NN + n4]) =
                make_float4(l0, h0, l1, h1);
            st[c] = (l0 + h0) + (l1 + h1);
            sq[c] = l0 * l0 + h0 * h0 + l1 * l1 + h1 * h1;
        }
    }
#pragma unroll
    for (int d = 1; d < 16; d <<= 1) {
#pragma unroll
        for (int c = 0; c < 4; c++) {
            st[c] += __shfl_xor_sync(0xffffffffu, st[c], d);
            sq[c] += __shfl_xor_sync(0xffffffffu, sq[c], d);
        }
    }
    if (rg == 0) {
#pragma unroll
        for (int c = 0; c < 4; c++) {
            atomicAdd(&g_stats[c20 + c], st[c]);
            atomicAdd(&g_stats[EMB + c20 + c], sq[c]);
        }
    }
}

// -------- normalize (+mish), transposed in, row-major out via smem tile -----
template <bool LAST>
__global__ __launch_bounds__(256) void norm_kernel(
    const float* __restrict__ gamma, const float* __restrict__ beta,
    float* __restrict__ outp) {
    __shared__ float sg[EMB], sb[EMB];
    __shared__ float sT[64 * 68];
    int tid = threadIdx.x;
    if (tid < EMB) {
        const float inv = 1.f / (float)NN;
        float mu = g_stats[tid] * inv;
        float var = g_stats[EMB + tid] * inv - mu * mu;
        float rs = rsqrtf(fmaxf(var, 0.f) + 1e-5f);
        float g = rs * gamma[tid];
        sg[tid] = g;
        sb[tid] = beta[tid] - mu * g;
    }
    __syncthreads();
    int node0 = blockIdx.x * 64;
#pragma unroll
    for (int it = 0; it < 4; it++) {
        int idx = it * 256 + tid;
        int ch = idx >> 4, m4 = (idx & 15) * 4;
        int n4 = node0 + m4;
        float4 v = make_float4(0.f, 0.f, 0.f, 0.f);
        if (n4 < NN)
            v = *reinterpret_cast<const float4*>(&g_hnT[(size_t)ch * NN + n4]);
        float vs[4] = {v.x, v.y, v.z, v.w};
        float gch = sg[ch], bch = sb[ch];
#pragma unroll
        for (int q = 0; q < 4; q++) {
            float y = fmaf(vs[q], gch, bch);
            if (!LAST) {
                float t = 1.f + __expf(y);
                y = y - __fdividef(2.f * y, fmaf(t, t, 1.f));
            }
            sT[(m4 + q) * 68 + ch] = y;
        }
    }
    __syncthreads();
    float* dst = LAST ? outp : g_h;
#pragma unroll
    for (int it = 0; it < 4; it++) {
        int idx = it * 256 + tid;
        int m = idx >> 4, c4 = (idx & 15) * 4;
        int n = node0 + m;
        if (n < NN) {
            float4 o = *reinterpret_cast<const float4*>(&sT[m * 68 + c4]);
            *reinterpret_cast<float4*>(&dst[(size_t)n * EMB + c4]) = o;
        }
    }
}

// ---------------- launch ----------------
extern "C" void kernel_launch(void* const* d_in, const int* in_sizes, int n_in,
                              void* d_out, int out_size) {
    const float* x = (const float*)d_in[0];
    const float* ea = (const float*)d_in[1];
    const float* Wemb = (const float*)d_in[2];
    const float* W1 = (const float*)d_in[3];
    const float* b1 = (const float*)d_in[4];
    const float* W2 = (const float*)d_in[5];
    const float* b2 = (const float*)d_in[6];
    const float* We = (const float*)d_in[7];
    const float* be = (const float*)d_in[8];
    const float* gamma = (const float*)d_in[9];
    const float* beta = (const float*)d_in[10];
    const int* ei = (const int*)d_in[11];
    float* out = (float*)d_out;

    cudaFuncSetAttribute(mlp_fused_kernel,
                         cudaFuncAttributeMaxDynamicSharedMemorySize, F_SMEM_BYTES);

    void* cntp = nullptr;
    cudaGetSymbolAddress(&cntp, g_cnt);
    cudaMemsetAsync(cntp, 0, NN * sizeof(int));

    const int nblk = (NN + 63) / 64;   // 782 blocks

    hist_embed_kernel<<<(NE + 255) / 256, 256>>>(ei, x, Wemb);   // 0
    chunk_scan_kernel<<<NCHUNK, 1024>>>();                       // 1
    scan_apply_kernel<<<NCHUNK, 1024>>>();                       // 2
    fill_kernel<<<(NE + 255) / 256, 256>>>(ei);                  // 3 (profiled)
    sgather_kernel<<<(NN * 32 + 255) / 256, 256>>>(ea);          // 4

    for (int l = 0; l < NLAYER; l++) {
        gather_kernel<<<(NN * 32 + 255) / 256, 256>>>(
            We + (size_t)l * EMB * BOND_F, be + (size_t)l * EMB);
        mlp_fused_kernel<<<nblk, 256, F_SMEM_BYTES>>>(
            W1 + (size_t)l * EMB2 * EMB, b1 + (size_t)l * EMB2,
            W2 + (size_t)l * EMB * EMB2, b2 + (size_t)l * EMB);
        if (l < NLAYER - 1)
            norm_kernel<false><<<nblk, 256>>>(
                gamma + (size_t)l * EMB, beta + (size_t)l * EMB, nullptr);
        else
            norm_kernel<true><<<nblk, 256>>>(
                gamma + (size_t)l * EMB, beta + (size_t)l * EMB, out);
    }
}

// round 15
// speedup vs baseline: 1.2922x; 1.0568x over previous
#include <cuda_runtime.h>
#include <math.h>

#define NLAYER 5
#define EMB 64
#define EMB2 128
#define ATOM_F 32
#define BOND_F 16
#define NN 50000
#define NE 800000
#define PW1 132
#define PH 68
#define PB 68
#define NCHUNK 49   // ceil(NN/1024)

typedef unsigned long long ull;

// ---------------- scratch (static device globals; no runtime alloc) ----------
__device__ float g_h[NN * EMB];              // row-major [n][64]
__device__ float g_hnT[(size_t)EMB * NN];    // transposed [col][n]
__device__ float g_S[NN * BOND_F];
__device__ float g_stats[NLAYER * 2 * EMB];  // per-layer slices
__device__ int   g_cnt[NN];
__device__ int   g_rowptr[NN + 1];
__device__ int   g_cur[NN];
__device__ int   g_blocksum[NCHUNK];
__device__ int   g_csr[NE];
__device__ int   g_src[NE];

// ---------------- f32x2 packed math ----------------
#define PACK2(d, x) asm("mov.b64 %0, {%1, %1};" : "=l"(d) : "r"(__float_as_uint(x)))
#define FMA2(d, a, b, c) asm("fma.rn.f32x2 %0, %1, %2, %3;" : "=l"(d) : "l"(a), "l"(b), "l"(c))
#define UNPACK2(lo, hi, v)                                            \
    {                                                                 \
        unsigned int u0_, u1_;                                        \
        asm("mov.b64 {%0, %1}, %2;" : "=r"(u0_), "=r"(u1_) : "l"(v)); \
        lo = __uint_as_float(u0_);                                    \
        hi = __uint_as_float(u1_);                                    \
    }

// -------- fused: histogram of dst + h = x @ Wemb^T ------
__global__ __launch_bounds__(256) void hist_embed_kernel(
    const int* __restrict__ ei, const float* __restrict__ x,
    const float* __restrict__ Wemb) {
    __shared__ float w[EMB * ATOM_F];
    int tid = threadIdx.x;
    for (int i = tid; i < EMB * ATOM_F; i += 256) w[i] = Wemb[i];
    __syncthreads();
    int gid = blockIdx.x * 256 + tid;
    if (gid < NE) atomicAdd(&g_cnt[ei[NE + gid]], 1);
    int node = gid >> 4;
    int j0 = (gid & 15) * 4;
    if (node < NN) {
        const float* xr = x + (size_t)node * ATOM_F;
        float a0 = 0.f, a1 = 0.f, a2 = 0.f, a3 = 0.f;
#pragma unroll
        for (int k = 0; k < ATOM_F; k++) {
            float xv = xr[k];
            a0 = fmaf(xv, w[(j0 + 0) * ATOM_F + k], a0);
            a1 = fmaf(xv, w[(j0 + 1) * ATOM_F + k], a1);
            a2 = fmaf(xv, w[(j0 + 2) * ATOM_F + k], a2);
            a3 = fmaf(xv, w[(j0 + 3) * ATOM_F + k], a3);
        }
        *reinterpret_cast<float4*>(&g_h[(size_t)node * EMB + j0]) =
            make_float4(a0, a1, a2, a3);
    }
}

// -------- parallel scan stage 1 --------
__global__ __launch_bounds__(1024) void chunk_scan_kernel() {
    __shared__ int warp_off[32];
    int tid = threadIdx.x;
    int lane = tid & 31, wid = tid >> 5;
    int i = blockIdx.x * 1024 + tid;
    int v = (i < NN) ? g_cnt[i] : 0;
    int x = v;
#pragma unroll
    for (int d = 1; d < 32; d <<= 1) {
        int y = __shfl_up_sync(0xffffffffu, x, d);
        if (lane >= d) x += y;
    }
    if (lane == 31) warp_off[wid] = x;
    __syncthreads();
    if (wid == 0) {
        int w = warp_off[lane];
        int xx = w;
#pragma unroll
        for (int d = 1; d < 32; d <<= 1) {
            int y = __shfl_up_sync(0xffffffffu, xx, d);
            if (lane >= d) xx += y;
        }
        warp_off[lane] = xx - w;
    }
    __syncthreads();
    int excl = warp_off[wid] + x - v;
    if (i < NN) g_rowptr[i] = excl;
    if (tid == 1023) g_blocksum[blockIdx.x] = excl + v;
}

// -------- parallel scan stage 2 --------
__global__ __launch_bounds__(1024) void scan_apply_kernel() {
    __shared__ int s_off;
    int tid = threadIdx.x;
    if (tid == 0) {
        int off = 0;
        for (int j = 0; j < (int)blockIdx.x; j++) off += g_blocksum[j];
        s_off = off;
        if (blockIdx.x == NCHUNK - 1)
            g_rowptr[NN] = off + g_blocksum[NCHUNK - 1];
    }
    __syncthreads();
    int i = blockIdx.x * 1024 + tid;
    if (i < NN) {
        int r = g_rowptr[i] + s_off;
        g_rowptr[i] = r;
        g_cur[i] = r;
    }
}

// ---------------- fill CSR buckets ----------------
__global__ void fill_kernel(const int* __restrict__ ei) {
    int e = blockIdx.x * blockDim.x + threadIdx.x;
    if (e >= NE) return;
    int dst = ei[NE + e];
    int pos = atomicAdd(&g_cur[dst], 1);
    g_csr[pos] = e;
    g_src[pos] = ei[e];
}

// ---------------- S[n] = sum of edge_attr over in-edges (once) ---------------
__global__ void sgather_kernel(const float* __restrict__ ea) {
    int gt = blockIdx.x * blockDim.x + threadIdx.x;
    int node = gt >> 5, lane = gt & 31;
    if (node >= NN) return;
    int beg = g_rowptr[node], end = g_rowptr[node + 1];
    float s = 0.f;
    for (int i = beg; i < end; i += 32) {
        int n = end - i;
        if (n > 32) n = 32;
        int eid = 0;
        if (lane < n) eid = g_csr[i + lane];
        for (int j = 0; j < n; j++) {
            int e = __shfl_sync(0xffffffffu, eid, j);
            if (lane < BOND_F) s += ea[(size_t)e * BOND_F + lane];
        }
    }
    if (lane < BOND_F) g_S[(size_t)node * BOND_F + lane] = s;
}

// ---------- fused layer kernel: per-tile gather + MLP + BN stats -----------
// Region0 (8704 floats): phase1 sW1T [64][PW1], phase2 sHid [128][PH]
// Region1 (4352 floats): gather+phase1 sBase [64][PB], phase2 sW2T half
#define F_SMEM_FLOATS (8704 + 4352 + 128 + 64 + BOND_F * EMB + 64)
#define F_SMEM_BYTES (F_SMEM_FLOATS * 4)

__global__ __launch_bounds__(256, 4) void gmlp_kernel(
    const float* __restrict__ W1l, const float* __restrict__ b1l,
    const float* __restrict__ W2l, const float* __restrict__ b2l,
    const float* __restrict__ Wel, const float* __restrict__ bel,
    float* __restrict__ statsl) {
    extern __shared__ float sm[];
    float* region0 = sm;               // 8704 floats
    float* region1 = sm + 8704;        // 4352 floats
    float* sB1 = sm + 8704 + 4352;     // 128
    float* sB2 = sB1 + 128;            // 64
    float* sWeT = sB2 + 64;            // [16][64]
    float* sBe = sWeT + BOND_F * EMB;  // 64

    float* sW1T = region0;             // [64 k][PW1] (phase 1)
    float* sHid = region0;             // [128 col][PH] (phase 2)
    float* sBase = region1;            // [64 k][PB]
    float* sW2T = region1;             // [64 kk][PH] (phase 2 halves)

    const int tid = threadIdx.x;
    const int node0 = blockIdx.x * 64;

    // ---- stage weights ----
    for (int idx = tid; idx < EMB2 * EMB; idx += 256) {
        int i = idx >> 6, k = idx & 63;
        sW1T[k * PW1 + i] = W1l[idx];
    }
    for (int idx = tid; idx < BOND_F * EMB; idx += 256) {
        int k = idx >> 6, j = idx & 63;
        sWeT[idx] = Wel[j * BOND_F + k];
    }
    if (tid < 128) sB1[tid] = b1l[tid];
    if (tid < 64) {
        sB2[tid] = b2l[tid];
        sBe[tid] = bel[tid];
    }
    __syncthreads();   // sWeT/sBe needed by gather epilogue below

    // ---- gather phase: warp w handles nodes node0+w*8 .. +7 ----
    {
        const int wid = tid >> 5, lane = tid & 31;
        const int half = lane >> 4, sub = lane & 15;
        for (int i8 = 0; i8 < 8; i8++) {
            int m = wid * 8 + i8;
            int node = node0 + m;
            if (node < NN) {
                int beg = g_rowptr[node], end = g_rowptr[node + 1];
                float4 acc0 = make_float4(0.f, 0.f, 0.f, 0.f);
                float4 acc1 = make_float4(0.f, 0.f, 0.f, 0.f);
                if (half == 0)
                    acc0 = *reinterpret_cast<const float4*>(
                        &g_h[(size_t)node * EMB + sub * 4]);
                for (int i = beg; i < end; i += 32) {
                    int n = end - i;
                    if (n > 32) n = 32;
                    int src = 0;
                    if (lane < n) src = g_src[i + lane];
                    int j = 0;
                    for (; j + 4 <= n; j += 4) {
                        int s0 = __shfl_sync(0xffffffffu, src, j + half);
                        int s1 = __shfl_sync(0xffffffffu, src, j + 2 + half);
                        float4 v0 = __ldg(reinterpret_cast<const float4*>(
                            &g_h[(size_t)s0 * EMB + sub * 4]));
                        float4 v1 = __ldg(reinterpret_cast<const float4*>(
                            &g_h[(size_t)s1 * EMB + sub * 4]));
                        acc0.x += v0.x; acc0.y += v0.y; acc0.z += v0.z; acc0.w += v0.w;
                        acc1.x += v1.x; acc1.y += v1.y; acc1.z += v1.z; acc1.w += v1.w;
                    }
                    if (j + 2 <= n) {
                        int s0 = __shfl_sync(0xffffffffu, src, j + half);
                        float4 v0 = __ldg(reinterpret_cast<const float4*>(
                            &g_h[(size_t)s0 * EMB + sub * 4]));
                        acc0.x += v0.x; acc0.y += v0.y; acc0.z += v0.z; acc0.w += v0.w;
                        j += 2;
                    }
                    if (j < n) {
                        int s0 = __shfl_sync(0xffffffffu, src, j);
                        if (half == 0) {
                            float4 v0 = __ldg(reinterpret_cast<const float4*>(
                                &g_h[(size_t)s0 * EMB + sub * 4]));
                            acc0.x += v0.x; acc0.y += v0.y; acc0.z += v0.z; acc0.w += v0.w;
                        }
                    }
                }
                acc0.x += acc1.x; acc0.y += acc1.y; acc0.z += acc1.z; acc0.w += acc1.w;
                acc0.x += __shfl_xor_sync(0xffffffffu, acc0.x, 16);
                acc0.y += __shfl_xor_sync(0xffffffffu, acc0.y, 16);
                acc0.z += __shfl_xor_sync(0xffffffffu, acc0.z, 16);
                acc0.w += __shfl_xor_sync(0xffffffffu, acc0.w, 16);
                if (half == 0) {
                    // edge-embed term: deg*be + S @ We^T for channels sub*4..+3
                    float deg = (float)(end - beg + 1);
                    const float4* sp = reinterpret_cast<const float4*>(
                        &g_S[(size_t)node * BOND_F]);
                    float4 s0 = sp[0], s1 = sp[1], s2 = sp[2], s3 = sp[3];
                    float se[16] = {s0.x, s0.y, s0.z, s0.w, s1.x, s1.y, s1.z, s1.w,
                                    s2.x, s2.y, s2.z, s2.w, s3.x, s3.y, s3.z, s3.w};
                    float4 be4 = *reinterpret_cast<const float4*>(&sBe[sub * 4]);
                    float4 ee;
                    ee.x = deg * be4.x; ee.y = deg * be4.y;
                    ee.z = deg * be4.z; ee.w = deg * be4.w;
#pragma unroll
                    for (int k = 0; k < BOND_F; k++) {
                        float4 w4 =
                            *reinterpret_cast<const float4*>(&sWeT[k * EMB + sub * 4]);
                        ee.x = fmaf(se[k], w4.x, ee.x);
                        ee.y = fmaf(se[k], w4.y, ee.y);
                        ee.z = fmaf(se[k], w4.z, ee.z);
                        ee.w = fmaf(se[k], w4.w, ee.w);
                    }
                    sBase[(sub * 4 + 0) * PB + m] = acc0.x + ee.x;
                    sBase[(sub * 4 + 1) * PB + m] = acc0.y + ee.y;
                    sBase[(sub * 4 + 2) * PB + m] = acc0.z + ee.z;
                    sBase[(sub * 4 + 3) * PB + m] = acc0.w + ee.w;
                }
            } else if (half == 0) {
                sBase[(sub * 4 + 0) * PB + m] = 0.f;
                sBase[(sub * 4 + 1) * PB + m] = 0.f;
                sBase[(sub * 4 + 2) * PB + m] = 0.f;
                sBase[(sub * 4 + 3) * PB + m] = 0.f;
            }
        }
    }
    __syncthreads();

    const int rg = tid & 15;          // rows rg*4 .. rg*4+3
    const int c0 = (tid >> 4) * 8;    // GEMM1 cols c0..c0+7
    const int c20 = (tid >> 4) * 4;   // GEMM2 cols c20..c20+3

    // ---- GEMM1: acc[2][8] over k=0..63 ----
    ull acc[2][8];
#pragma unroll
    for (int r = 0; r < 2; r++)
#pragma unroll
        for (int c = 0; c < 8; c++) acc[r][c] = 0ull;
#pragma unroll 4
    for (int k = 0; k < EMB; k++) {
        ulonglong2 A = *reinterpret_cast<const ulonglong2*>(&sBase[k * PB + rg * 4]);
        ull ap0 = A.x, ap1 = A.y;
        {
            float4 wq = *reinterpret_cast<const float4*>(&sW1T[k * PW1 + c0]);
            ull w0, w1, w2, w3;
            PACK2(w0, wq.x); PACK2(w1, wq.y); PACK2(w2, wq.z); PACK2(w3, wq.w);
            FMA2(acc[0][0], ap0, w0, acc[0][0]); FMA2(acc[1][0], ap1, w0, acc[1][0]);
            FMA2(acc[0][1], ap0, w1, acc[0][1]); FMA2(acc[1][1], ap1, w1, acc[1][1]);
            FMA2(acc[0][2], ap0, w2, acc[0][2]); FMA2(acc[1][2], ap1, w2, acc[1][2]);
            FMA2(acc[0][3], ap0, w3, acc[0][3]); FMA2(acc[1][3], ap1, w3, acc[1][3]);
        }
        {
            float4 wq = *reinterpret_cast<const float4*>(&sW1T[k * PW1 + c0 + 4]);
            ull w0, w1, w2, w3;
            PACK2(w0, wq.x); PACK2(w1, wq.y); PACK2(w2, wq.z); PACK2(w3, wq.w);
            FMA2(acc[0][4], ap0, w0, acc[0][4]); FMA2(acc[1][4], ap1, w0, acc[1][4]);
            FMA2(acc[0][5], ap0, w1, acc[0][5]); FMA2(acc[1][5], ap1, w1, acc[1][5]);
            FMA2(acc[0][6], ap0, w2, acc[0][6]); FMA2(acc[1][6], ap1, w2, acc[1][6]);
            FMA2(acc[0][7], ap0, w3, acc[0][7]); FMA2(acc[1][7], ap1, w3, acc[1][7]);
        }
    }
    __syncthreads();   // all reads of sW1T/sBase done — regions reusable

    // ---- hid = relu(acc + b1) into sHid[col][m] (region0) ----
#pragma unroll
    for (int p = 0; p < 8; p++) {
        int col = c0 + p;
        float b = sB1[col];
        float l0, h0, l1, h1;
        UNPACK2(l0, h0, acc[0][p]);
        UNPACK2(l1, h1, acc[1][p]);
        float4 o = make_float4(fmaxf(l0 + b, 0.f), fmaxf(h0 + b, 0.f),
                               fmaxf(l1 + b, 0.f), fmaxf(h1 + b, 0.f));
        *reinterpret_cast<float4*>(&sHid[col * PH + rg * 4]) = o;
    }

    // ---- GEMM2 in two k-halves, W2 staged into region1 ----
    ull acc2[2][4];
#pragma unroll
    for (int r = 0; r < 2; r++)
#pragma unroll
        for (int c = 0; c < 4; c++) acc2[r][c] = 0ull;

#pragma unroll
    for (int kh = 0; kh < 2; kh++) {
        __syncthreads();  // hid writes done (kh=0) / prior W2 half reads done
        for (int idx = tid; idx < 64 * 64; idx += 256) {
            int j = idx >> 6, kk = idx & 63;
            sW2T[kk * PH + j] = W2l[j * EMB2 + kh * 64 + kk];
        }
        __syncthreads();
#pragma unroll 4
        for (int k = 0; k < 64; k++) {
            ulonglong2 A = *reinterpret_cast<const ulonglong2*>(
                &sHid[(kh * 64 + k) * PH + rg * 4]);
            ull ap0 = A.x, ap1 = A.y;
            float4 wq = *reinterpret_cast<const float4*>(&sW2T[k * PH + c20]);
            ull w0, w1, w2, w3;
            PACK2(w0, wq.x); PACK2(w1, wq.y); PACK2(w2, wq.z); PACK2(w3, wq.w);
            FMA2(acc2[0][0], ap0, w0, acc2[0][0]); FMA2(acc2[1][0], ap1, w0, acc2[1][0]);
            FMA2(acc2[0][1], ap0, w1, acc2[0][1]); FMA2(acc2[1][1], ap1, w1, acc2[1][1]);
            FMA2(acc2[0][2], ap0, w2, acc2[0][2]); FMA2(acc2[1][2], ap1, w2, acc2[1][2]);
            FMA2(acc2[0][3], ap0, w3, acc2[0][3]); FMA2(acc2[1][3], ap1, w3, acc2[1][3]);
        }
    }

    // ---- epilogue: hnT + BN partial stats ----
    int n4 = node0 + rg * 4;
    float st[4] = {0.f, 0.f, 0.f, 0.f};
    float sq[4] = {0.f, 0.f, 0.f, 0.f};
    if (n4 < NN) {
#pragma unroll
        for (int c = 0; c < 4; c++) {
            int col = c20 + c;
            float b = sB2[col];
            float l0, h0, l1, h1;
            UNPACK2(l0, h0, acc2[0][c]);
            UNPACK2(l1, h1, acc2[1][c]);
            l0 += b; h0 += b; l1 += b; h1 += b;
            *reinterpret_cast<float4*>(&g_hnT[(size_t)col * NN + n4]) =
                make_float4(l0, h0, l1, h1);
            st[c] = (l0 + h0) + (l1 + h1);
            sq[c] = l0 * l0 + h0 * h0 + l1 * l1 + h1 * h1;
        }
    }
#pragma unroll
    for (int d = 1; d < 16; d <<= 1) {
#pragma unroll
        for (int c = 0; c < 4; c++) {
            st[c] += __shfl_xor_sync(0xffffffffu, st[c], d);
            sq[c] += __shfl_xor_sync(0xffffffffu, sq[c], d);
        }
    }
    if (rg == 0) {
#pragma unroll
        for (int c = 0; c < 4; c++) {
            atomicAdd(&statsl[c20 + c], st[c]);
            atomicAdd(&statsl[EMB + c20 + c], sq[c]);
        }
    }
}

// -------- normalize (+mish), transposed in, row-major out via smem tile -----
template <bool LAST>
__global__ __launch_bounds__(256) void norm_kernel(
    const float* __restrict__ statsl,
    const float* __restrict__ gamma, const float* __restrict__ beta,
    float* __restrict__ outp) {
    __shared__ float sg[EMB], sb[EMB];
    __shared__ float sT[64 * 68];
    int tid = threadIdx.x;
    if (tid < EMB) {
        const float inv = 1.f / (float)NN;
        float mu = statsl[tid] * inv;
        float var = statsl[EMB + tid] * inv - mu * mu;
        float rs = rsqrtf(fmaxf(var, 0.f) + 1e-5f);
        float g = rs * gamma[tid];
        sg[tid] = g;
        sb[tid] = beta[tid] - mu * g;
    }
    __syncthreads();
    int node0 = blockIdx.x * 64;
#pragma unroll
    for (int it = 0; it < 4; it++) {
        int idx = it * 256 + tid;
        int ch = idx >> 4, m4 = (idx & 15) * 4;
        int n4 = node0 + m4;
        float4 v = make_float4(0.f, 0.f, 0.f, 0.f);
        if (n4 < NN)
            v = *reinterpret_cast<const float4*>(&g_hnT[(size_t)ch * NN + n4]);
        float vs[4] = {v.x, v.y, v.z, v.w};
        float gch = sg[ch], bch = sb[ch];
#pragma unroll
        for (int q = 0; q < 4; q++) {
            float y = fmaf(vs[q], gch, bch);
            if (!LAST) {
                float t = 1.f + __expf(y);
                y = y - __fdividef(2.f * y, fmaf(t, t, 1.f));
            }
            sT[(m4 + q) * 68 + ch] = y;
        }
    }
    __syncthreads();
    float* dst = LAST ? outp : g_h;
#pragma unroll
    for (int it = 0; it < 4; it++) {
        int idx = it * 256 + tid;
        int m = idx >> 4, c4 = (idx & 15) * 4;
        int n = node0 + m;
        if (n < NN) {
            float4 o = *reinterpret_cast<const float4*>(&sT[m * 68 + c4]);
            *reinterpret_cast<float4*>(&dst[(size_t)n * EMB + c4]) = o;
        }
    }
}

// ---------------- launch ----------------
extern "C" void kernel_launch(void* const* d_in, const int* in_sizes, int n_in,
                              void* d_out, int out_size) {
    const float* x = (const float*)d_in[0];
    const float* ea = (const float*)d_in[1];
    const float* Wemb = (const float*)d_in[2];
    const float* W1 = (const float*)d_in[3];
    const float* b1 = (const float*)d_in[4];
    const float* W2 = (const float*)d_in[5];
    const float* b2 = (const float*)d_in[6];
    const float* We = (const float*)d_in[7];
    const float* be = (const float*)d_in[8];
    const float* gamma = (const float*)d_in[9];
    const float* beta = (const float*)d_in[10];
    const int* ei = (const int*)d_in[11];
    float* out = (float*)d_out;

    cudaFuncSetAttribute(gmlp_kernel,
                         cudaFuncAttributeMaxDynamicSharedMemorySize, F_SMEM_BYTES);

    void* cntp = nullptr;
    cudaGetSymbolAddress(&cntp, g_cnt);
    cudaMemsetAsync(cntp, 0, NN * sizeof(int));
    void* statp = nullptr;
    cudaGetSymbolAddress(&statp, g_stats);
    cudaMemsetAsync(statp, 0, NLAYER * 2 * EMB * sizeof(float));

    float* statbase = (float*)statp;
    const int nblk = (NN + 63) / 64;   // 782 blocks

    hist_embed_kernel<<<(NE + 255) / 256, 256>>>(ei, x, Wemb);   // 0
    chunk_scan_kernel<<<NCHUNK, 1024>>>();                       // 1
    scan_apply_kernel<<<NCHUNK, 1024>>>();                       // 2
    fill_kernel<<<(NE + 255) / 256, 256>>>(ei);                  // 3 (profiled)
    sgather_kernel<<<(NN * 32 + 255) / 256, 256>>>(ea);          // 4

    for (int l = 0; l < NLAYER; l++) {
        float* statsl = statbase + (size_t)l * 2 * EMB;
        gmlp_kernel<<<nblk, 256, F_SMEM_BYTES>>>(
            W1 + (size_t)l * EMB2 * EMB, b1 + (size_t)l * EMB2,
            W2 + (size_t)l * EMB * EMB2, b2 + (size_t)l * EMB,
            We + (size_t)l * EMB * BOND_F, be + (size_t)l * EMB, statsl);
        if (l < NLAYER - 1)
            norm_kernel<false><<<nblk, 256>>>(
                statsl, gamma + (size_t)l * EMB, beta + (size_t)l * EMB, nullptr);
        else
            norm_kernel<true><<<nblk, 256>>>(
                statsl, gamma + (size_t)l * EMB, beta + (size_t)l * EMB, out);
    }
}

// round 17
// speedup vs baseline: 1.3210x; 1.0223x over previous
#include <cuda_runtime.h>
#include <math.h>

#define NLAYER 5
#define EMB 64
#define EMB2 128
#define ATOM_F 32
#define BOND_F 16
#define NN 50000
#define NE 800000
#define PW1 132
#define PH 68
#define PB 68
#define NCHUNK 49   // ceil(NN/1024)

typedef unsigned long long ull;

// ---------------- scratch (static device globals; no runtime alloc) ----------
__device__ float g_h[NN * EMB];              // row-major [n][64]
__device__ float g_hnT[(size_t)EMB * NN];    // transposed [col][n]
__device__ float g_S[NN * BOND_F];
__device__ float g_stats[NLAYER * 2 * EMB];  // per-layer slices
__device__ int   g_cnt[NN];
__device__ int   g_rowptr[NN + 1];
__device__ int   g_cur[NN];
__device__ int   g_chunkagg[NCHUNK];
__device__ volatile int g_chunkflag[NCHUNK];
__device__ int   g_csr[NE];
__device__ int   g_src[NE];

// ---------------- f32x2 packed math ----------------
#define PACK2(d, x) asm("mov.b64 %0, {%1, %1};" : "=l"(d) : "r"(__float_as_uint(x)))
#define FMA2(d, a, b, c) asm("fma.rn.f32x2 %0, %1, %2, %3;" : "=l"(d) : "l"(a), "l"(b), "l"(c))
#define UNPACK2(lo, hi, v)                                            \
    {                                                                 \
        unsigned int u0_, u1_;                                        \
        asm("mov.b64 {%0, %1}, %2;" : "=r"(u0_), "=r"(u1_) : "l"(v)); \
        lo = __uint_as_float(u0_);                                    \
        hi = __uint_as_float(u1_);                                    \
    }

// -------- fused: histogram of dst + h = x @ Wemb^T ------
__global__ __launch_bounds__(256) void hist_embed_kernel(
    const int* __restrict__ ei, const float* __restrict__ x,
    const float* __restrict__ Wemb) {
    __shared__ float w[EMB * ATOM_F];
    int tid = threadIdx.x;
    for (int i = tid; i < EMB * ATOM_F; i += 256) w[i] = Wemb[i];
    __syncthreads();
    int gid = blockIdx.x * 256 + tid;
    if (gid < NE) atomicAdd(&g_cnt[ei[NE + gid]], 1);
    int node = gid >> 4;
    int j0 = (gid & 15) * 4;
    if (node < NN) {
        const float* xr = x + (size_t)node * ATOM_F;
        float a0 = 0.f, a1 = 0.f, a2 = 0.f, a3 = 0.f;
#pragma unroll
        for (int k = 0; k < ATOM_F; k++) {
            float xv = xr[k];
            a0 = fmaf(xv, w[(j0 + 0) * ATOM_F + k], a0);
            a1 = fmaf(xv, w[(j0 + 1) * ATOM_F + k], a1);
            a2 = fmaf(xv, w[(j0 + 2) * ATOM_F + k], a2);
            a3 = fmaf(xv, w[(j0 + 3) * ATOM_F + k], a3);
        }
        *reinterpret_cast<float4*>(&g_h[(size_t)node * EMB + j0]) =
            make_float4(a0, a1, a2, a3);
    }
}

// -------- single-kernel decoupled scan (49 blocks, all resident) --------
__global__ __launch_bounds__(1024) void scan_kernel() {
    __shared__ int warp_off[32];
    __shared__ int s_off;
    int tid = threadIdx.x;
    int lane = tid & 31, wid = tid >> 5;
    int b = blockIdx.x;
    int i = b * 1024 + tid;
    int v = (i < NN) ? g_cnt[i] : 0;
    int x = v;
#pragma unroll
    for (int d = 1; d < 32; d <<= 1) {
        int y = __shfl_up_sync(0xffffffffu, x, d);
        if (lane >= d) x += y;
    }
    if (lane == 31) warp_off[wid] = x;
    __syncthreads();
    if (wid == 0) {
        int w = warp_off[lane];
        int xx = w;
#pragma unroll
        for (int d = 1; d < 32; d <<= 1) {
            int y = __shfl_up_sync(0xffffffffu, xx, d);
            if (lane >= d) xx += y;
        }
        warp_off[lane] = xx - w;
    }
    __syncthreads();
    int excl = warp_off[wid] + x - v;
    // publish this chunk's aggregate
    if (tid == 1023) {
        g_chunkagg[b] = excl + v;
        __threadfence();
        g_chunkflag[b] = 1;
    }
    // lookback: sum predecessors (all 49 blocks are resident — no deadlock)
    if (tid == 0) {
        int off = 0;
        for (int j = 0; j < b; j++) {
            while (g_chunkflag[j] == 0) {}
            off += g_chunkagg[j];
        }
        s_off = off;
    }
    __syncthreads();
    int off = s_off;
    if (i < NN) {
        int r = excl + off;
        g_rowptr[i] = r;
        g_cur[i] = r;
    }
    if (b == NCHUNK - 1 && tid == 1023) g_rowptr[NN] = off + excl + v;
}

// ---------------- fill CSR buckets ----------------
__global__ void fill_kernel(const int* __restrict__ ei) {
    int e = blockIdx.x * blockDim.x + threadIdx.x;
    if (e >= NE) return;
    int dst = ei[NE + e];
    int pos = atomicAdd(&g_cur[dst], 1);
    g_csr[pos] = e;
    g_src[pos] = ei[e];
}

// ------- S[n] = sum of edge_attr over in-edges; 8 edges x 4 lanes/warp ------
__global__ __launch_bounds__(256) void sgather_kernel(const float* __restrict__ ea) {
    int gt = blockIdx.x * blockDim.x + threadIdx.x;
    int node = gt >> 5, lane = gt & 31;
    if (node >= NN) return;
    const int e4 = lane >> 2, q = lane & 3;
    int beg = g_rowptr[node], end = g_rowptr[node + 1];
    float4 sacc = make_float4(0.f, 0.f, 0.f, 0.f);
    for (int i = beg; i < end; i += 8) {
        int ecsr = 0;
        if (lane < 8 && i + lane < end) ecsr = g_csr[i + lane];
        int eid = __shfl_sync(0xffffffffu, ecsr, e4);
        if (i + e4 < end) {
            float4 v = __ldg(reinterpret_cast<const float4*>(
                &ea[(size_t)eid * BOND_F + q * 4]));
            sacc.x += v.x; sacc.y += v.y; sacc.z += v.z; sacc.w += v.w;
        }
    }
    // reduce across the 8 edge-groups; lanes with equal q end up identical
#pragma unroll
    for (int d = 4; d < 32; d <<= 1) {
        sacc.x += __shfl_xor_sync(0xffffffffu, sacc.x, d);
        sacc.y += __shfl_xor_sync(0xffffffffu, sacc.y, d);
        sacc.z += __shfl_xor_sync(0xffffffffu, sacc.z, d);
        sacc.w += __shfl_xor_sync(0xffffffffu, sacc.w, d);
    }
    // lane L (<4) holds totals for features L*4..L*4+3 (its own quad q==L)
    if (lane < 4)
        *reinterpret_cast<float4*>(&g_S[(size_t)node * BOND_F + lane * 4]) = sacc;
}

// ---------- fused layer kernel: per-tile gather + MLP + BN stats -----------
#define F_SMEM_FLOATS (8704 + 4352 + 128 + 64 + BOND_F * EMB + 64)
#define F_SMEM_BYTES (F_SMEM_FLOATS * 4)

__global__ __launch_bounds__(256, 4) void gmlp_kernel(
    const float* __restrict__ W1l, const float* __restrict__ b1l,
    const float* __restrict__ W2l, const float* __restrict__ b2l,
    const float* __restrict__ Wel, const float* __restrict__ bel,
    float* __restrict__ statsl) {
    extern __shared__ float sm[];
    float* region0 = sm;               // 8704 floats
    float* region1 = sm + 8704;        // 4352 floats
    float* sB1 = sm + 8704 + 4352;     // 128
    float* sB2 = sB1 + 128;            // 64
    float* sWeT = sB2 + 64;            // [16][64]
    float* sBe = sWeT + BOND_F * EMB;  // 64

    float* sW1T = region0;             // [64 k][PW1] (phase 1)
    float* sHid = region0;             // [128 col][PH] (phase 2)
    float* sBase = region1;            // [64 k][PB]
    float* sW2T = region1;             // [64 kk][PH] (phase 2 halves)

    const int tid = threadIdx.x;
    const int node0 = blockIdx.x * 64;

    // ---- stage weights ----
    for (int idx = tid; idx < EMB2 * EMB; idx += 256) {
        int i = idx >> 6, k = idx & 63;
        sW1T[k * PW1 + i] = W1l[idx];
    }
    for (int idx = tid; idx < BOND_F * EMB; idx += 256) {
        int k = idx >> 6, j = idx & 63;
        sWeT[idx] = Wel[j * BOND_F + k];
    }
    if (tid < 128) sB1[tid] = b1l[tid];
    if (tid < 64) {
        sB2[tid] = b2l[tid];
        sBe[tid] = bel[tid];
    }
    __syncthreads();   // sWeT/sBe needed by gather epilogue below

    // ---- gather phase: warp w handles nodes node0+w*8 .. +7 ----
    {
        const int wid = tid >> 5, lane = tid & 31;
        const int half = lane >> 4, sub = lane & 15;
        for (int i8 = 0; i8 < 8; i8++) {
            int m = wid * 8 + i8;
            int node = node0 + m;
            if (node < NN) {
                int beg = g_rowptr[node], end = g_rowptr[node + 1];
                float4 a0 = make_float4(0.f, 0.f, 0.f, 0.f);
                float4 a1 = make_float4(0.f, 0.f, 0.f, 0.f);
                float4 a2 = make_float4(0.f, 0.f, 0.f, 0.f);
                float4 a3 = make_float4(0.f, 0.f, 0.f, 0.f);
                if (half == 0)
                    a0 = *reinterpret_cast<const float4*>(
                        &g_h[(size_t)node * EMB + sub * 4]);
                for (int i = beg; i < end; i += 32) {
                    int n = end - i;
                    if (n > 32) n = 32;
                    int src = 0;
                    if (lane < n) src = g_src[i + lane];
                    int j = 0;
                    for (; j + 8 <= n; j += 8) {
                        int s0 = __shfl_sync(0xffffffffu, src, j + half);
                        int s1 = __shfl_sync(0xffffffffu, src, j + 2 + half);
                        int s2 = __shfl_sync(0xffffffffu, src, j + 4 + half);
                        int s3 = __shfl_sync(0xffffffffu, src, j + 6 + half);
                        float4 v0 = __ldg(reinterpret_cast<const float4*>(
                            &g_h[(size_t)s0 * EMB + sub * 4]));
                        float4 v1 = __ldg(reinterpret_cast<const float4*>(
                            &g_h[(size_t)s1 * EMB + sub * 4]));
                        float4 v2 = __ldg(reinterpret_cast<const float4*>(
                            &g_h[(size_t)s2 * EMB + sub * 4]));
                        float4 v3 = __ldg(reinterpret_cast<const float4*>(
                            &g_h[(size_t)s3 * EMB + sub * 4]));
                        a0.x += v0.x; a0.y += v0.y; a0.z += v0.z; a0.w += v0.w;
                        a1.x += v1.x; a1.y += v1.y; a1.z += v1.z; a1.w += v1.w;
                        a2.x += v2.x; a2.y += v2.y; a2.z += v2.z; a2.w += v2.w;
                        a3.x += v3.x; a3.y += v3.y; a3.z += v3.z; a3.w += v3.w;
                    }
                    for (; j + 2 <= n; j += 2) {
                        int s0 = __shfl_sync(0xffffffffu, src, j + half);
                        float4 v0 = __ldg(reinterpret_cast<const float4*>(
                            &g_h[(size_t)s0 * EMB + sub * 4]));
                        a0.x += v0.x; a0.y += v0.y; a0.z += v0.z; a0.w += v0.w;
                    }
                    if (j < n) {
                        int s0 = __shfl_sync(0xffffffffu, src, j);
                        if (half == 0) {
                            float4 v0 = __ldg(reinterpret_cast<const float4*>(
                                &g_h[(size_t)s0 * EMB + sub * 4]));
                            a0.x += v0.x; a0.y += v0.y; a0.z += v0.z; a0.w += v0.w;
                        }
                    }
                }
                a0.x += a1.x + a2.x + a3.x;
                a0.y += a1.y + a2.y + a3.y;
                a0.z += a1.z + a2.z + a3.z;
                a0.w += a1.w + a2.w + a3.w;
                a0.x += __shfl_xor_sync(0xffffffffu, a0.x, 16);
                a0.y += __shfl_xor_sync(0xffffffffu, a0.y, 16);
                a0.z += __shfl_xor_sync(0xffffffffu, a0.z, 16);
                a0.w += __shfl_xor_sync(0xffffffffu, a0.w, 16);
                if (half == 0) {
                    // edge-embed term: deg*be + S @ We^T for channels sub*4..+3
                    float deg = (float)(end - beg + 1);
                    const float4* sp = reinterpret_cast<const float4*>(
                        &g_S[(size_t)node * BOND_F]);
                    float4 s0 = sp[0], s1 = sp[1], s2 = sp[2], s3 = sp[3];
                    float se[16] = {s0.x, s0.y, s0.z, s0.w, s1.x, s1.y, s1.z, s1.w,
                                    s2.x, s2.y, s2.z, s2.w, s3.x, s3.y, s3.z, s3.w};
                    float4 be4 = *reinterpret_cast<const float4*>(&sBe[sub * 4]);
                    float4 ee;
                    ee.x = deg * be4.x; ee.y = deg * be4.y;
                    ee.z = deg * be4.z; ee.w = deg * be4.w;
#pragma unroll
                    for (int k = 0; k < BOND_F; k++) {
                        float4 w4 =
                            *reinterpret_cast<const float4*>(&sWeT[k * EMB + sub * 4]);
                        ee.x = fmaf(se[k], w4.x, ee.x);
                        ee.y = fmaf(se[k], w4.y, ee.y);
                        ee.z = fmaf(se[k], w4.z, ee.z);
                        ee.w = fmaf(se[k], w4.w, ee.w);
                    }
                    sBase[(sub * 4 + 0) * PB + m] = a0.x + ee.x;
                    sBase[(sub * 4 + 1) * PB + m] = a0.y + ee.y;
                    sBase[(sub * 4 + 2) * PB + m] = a0.z + ee.z;
                    sBase[(sub * 4 + 3) * PB + m] = a0.w + ee.w;
                }
            } else if (half == 0) {
                sBase[(sub * 4 + 0) * PB + m] = 0.f;
                sBase[(sub * 4 + 1) * PB + m] = 0.f;
                sBase[(sub * 4 + 2) * PB + m] = 0.f;
                sBase[(sub * 4 + 3) * PB + m] = 0.f;
            }
        }
    }
    __syncthreads();

    const int rg = tid & 15;          // rows rg*4 .. rg*4+3
    const int c0 = (tid >> 4) * 8;    // GEMM1 cols c0..c0+7
    const int c20 = (tid >> 4) * 4;   // GEMM2 cols c20..c20+3

    // ---- GEMM1: acc[2][8] over k=0..63 ----
    ull acc[2][8];
#pragma unroll
    for (int r = 0; r < 2; r++)
#pragma unroll
        for (int c = 0; c < 8; c++) acc[r][c] = 0ull;
#pragma unroll 4
    for (int k = 0; k < EMB; k++) {
        ulonglong2 A = *reinterpret_cast<const ulonglong2*>(&sBase[k * PB + rg * 4]);
        ull ap0 = A.x, ap1 = A.y;
        {
            float4 wq = *reinterpret_cast<const float4*>(&sW1T[k * PW1 + c0]);
            ull w0, w1, w2, w3;
            PACK2(w0, wq.x); PACK2(w1, wq.y); PACK2(w2, wq.z); PACK2(w3, wq.w);
            FMA2(acc[0][0], ap0, w0, acc[0][0]); FMA2(acc[1][0], ap1, w0, acc[1][0]);
            FMA2(acc[0][1], ap0, w1, acc[0][1]); FMA2(acc[1][1], ap1, w1, acc[1][1]);
            FMA2(acc[0][2], ap0, w2, acc[0][2]); FMA2(acc[1][2], ap1, w2, acc[1][2]);
            FMA2(acc[0][3], ap0, w3, acc[0][3]); FMA2(acc[1][3], ap1, w3, acc[1][3]);
        }
        {
            float4 wq = *reinterpret_cast<const float4*>(&sW1T[k * PW1 + c0 + 4]);
            ull w0, w1, w2, w3;
            PACK2(w0, wq.x); PACK2(w1, wq.y); PACK2(w2, wq.z); PACK2(w3, wq.w);
            FMA2(acc[0][4], ap0, w0, acc[0][4]); FMA2(acc[1][4], ap1, w0, acc[1][4]);
            FMA2(acc[0][5], ap0, w1, acc[0][5]); FMA2(acc[1][5], ap1, w1, acc[1][5]);
            FMA2(acc[0][6], ap0, w2, acc[0][6]); FMA2(acc[1][6], ap1, w2, acc[1][6]);
            FMA2(acc[0][7], ap0, w3, acc[0][7]); FMA2(acc[1][7], ap1, w3, acc[1][7]);
        }
    }
    __syncthreads();   // all reads of sW1T/sBase done — regions reusable

    // ---- hid = relu(acc + b1) into sHid[col][m] (region0) ----
#pragma unroll
    for (int p = 0; p < 8; p++) {
        int col = c0 + p;
        float b = sB1[col];
        float l0, h0, l1, h1;
        UNPACK2(l0, h0, acc[0][p]);
        UNPACK2(l1, h1, acc[1][p]);
        float4 o = make_float4(fmaxf(l0 + b, 0.f), fmaxf(h0 + b, 0.f),
                               fmaxf(l1 + b, 0.f), fmaxf(h1 + b, 0.f));
        *reinterpret_cast<float4*>(&sHid[col * PH + rg * 4]) = o;
    }

    // ---- GEMM2 in two k-halves, W2 staged into region1 ----
    ull acc2[2][4];
#pragma unroll
    for (int r = 0; r < 2; r++)
#pragma unroll
        for (int c = 0; c < 4; c++) acc2[r][c] = 0ull;

#pragma unroll
    for (int kh = 0; kh < 2; kh++) {
        __syncthreads();  // hid writes done (kh=0) / prior W2 half reads done
        for (int idx = tid; idx < 64 * 64; idx += 256) {
            int j = idx >> 6, kk = idx & 63;
            sW2T[kk * PH + j] = W2l[j * EMB2 + kh * 64 + kk];
        }
        __syncthreads();
#pragma unroll 4
        for (int k = 0; k < 64; k++) {
            ulonglong2 A = *reinterpret_cast<const ulonglong2*>(
                &sHid[(kh * 64 + k) * PH + rg * 4]);
            ull ap0 = A.x, ap1 = A.y;
            float4 wq = *reinterpret_cast<const float4*>(&sW2T[k * PH + c20]);
            ull w0, w1, w2, w3;
            PACK2(w0, wq.x); PACK2(w1, wq.y); PACK2(w2, wq.z); PACK2(w3, wq.w);
            FMA2(acc2[0][0], ap0, w0, acc2[0][0]); FMA2(acc2[1][0], ap1, w0, acc2[1][0]);
            FMA2(acc2[0][1], ap0, w1, acc2[0][1]); FMA2(acc2[1][1], ap1, w1, acc2[1][1]);
            FMA2(acc2[0][2], ap0, w2, acc2[0][2]); FMA2(acc2[1][2], ap1, w2, acc2[1][2]);
            FMA2(acc2[0][3], ap0, w3, acc2[0][3]); FMA2(acc2[1][3], ap1, w3, acc2[1][3]);
        }
    }

    // ---- epilogue: hnT + BN partial stats ----
    int n4 = node0 + rg * 4;
    float st[4] = {0.f, 0.f, 0.f, 0.f};
    float sq[4] = {0.f, 0.f, 0.f, 0.f};
    if (n4 < NN) {
#pragma unroll
        for (int c = 0; c < 4; c++) {
            int col = c20 + c;
            float b = sB2[col];
            float l0, h0, l1, h1;
            UNPACK2(l0, h0, acc2[0][c]);
            UNPACK2(l1, h1, acc2[1][c]);
            l0 += b; h0 += b; l1 += b; h1 += b;
            *reinterpret_cast<float4*>(&g_hnT[(size_t)col * NN + n4]) =
                make_float4(l0, h0, l1, h1);
            st[c] = (l0 + h0) + (l1 + h1);
            sq[c] = l0 * l0 + h0 * h0 + l1 * l1 + h1 * h1;
        }
    }
#pragma unroll
    for (int d = 1; d < 16; d <<= 1) {
#pragma unroll
        for (int c = 0; c < 4; c++) {
            st[c] += __shfl_xor_sync(0xffffffffu, st[c], d);
            sq[c] += __shfl_xor_sync(0xffffffffu, sq[c], d);
        }
    }
    if (rg == 0) {
#pragma unroll
        for (int c = 0; c < 4; c++) {
            atomicAdd(&statsl[c20 + c], st[c]);
            atomicAdd(&statsl[EMB + c20 + c], sq[c]);
        }
    }
}

// -------- normalize (+mish), transposed in, row-major out via smem tile -----
template <bool LAST>
__global__ __launch_bounds__(256) void norm_kernel(
    const float* __restrict__ statsl,
    const float* __restrict__ gamma, const float* __restrict__ beta,
    float* __restrict__ outp) {
    __shared__ float sg[EMB], sb[EMB];
    __shared__ float sT[64 * 68];
    int tid = threadIdx.x;
    if (tid < EMB) {
        const float inv = 1.f / (float)NN;
        float mu = statsl[tid] * inv;
        float var = statsl[EMB + tid] * inv - mu * mu;
        float rs = rsqrtf(fmaxf(var, 0.f) + 1e-5f);
        float g = rs * gamma[tid];
        sg[tid] = g;
        sb[tid] = beta[tid] - mu * g;
    }
    __syncthreads();
    int node0 = blockIdx.x * 64;
#pragma unroll
    for (int it = 0; it < 4; it++) {
        int idx = it * 256 + tid;
        int ch = idx >> 4, m4 = (idx & 15) * 4;
        int n4 = node0 + m4;
        float4 v = make_float4(0.f, 0.f, 0.f, 0.f);
        if (n4 < NN)
            v = *reinterpret_cast<const float4*>(&g_hnT[(size_t)ch * NN + n4]);
        float vs[4] = {v.x, v.y, v.z, v.w};
        float gch = sg[ch], bch = sb[ch];
#pragma unroll
        for (int q = 0; q < 4; q++) {
            float y = fmaf(vs[q], gch, bch);
            if (!LAST) {
                float t = 1.f + __expf(y);
                y = y - __fdividef(2.f * y, fmaf(t, t, 1.f));
            }
            sT[(m4 + q) * 68 + ch] = y;
        }
    }
    __syncthreads();
    float* dst = LAST ? outp : g_h;
#pragma unroll
    for (int it = 0; it < 4; it++) {
        int idx = it * 256 + tid;
        int m = idx >> 4, c4 = (idx & 15) * 4;
        int n = node0 + m;
        if (n < NN) {
            float4 o = *reinterpret_cast<const float4*>(&sT[m * 68 + c4]);
            *reinterpret_cast<float4*>(&dst[(size_t)n * EMB + c4]) = o;
        }
    }
}

// ---------------- launch ----------------
extern "C" void kernel_launch(void* const* d_in, const int* in_sizes, int n_in,
                              void* d_out, int out_size) {
    const float* x = (const float*)d_in[0];
    const float* ea = (const float*)d_in[1];
    const float* Wemb = (const float*)d_in[2];
    const float* W1 = (const float*)d_in[3];
    const float* b1 = (const float*)d_in[4];
    const float* W2 = (const float*)d_in[5];
    const float* b2 = (const float*)d_in[6];
    const float* We = (const float*)d_in[7];
    const float* be = (const float*)d_in[8];
    const float* gamma = (const float*)d_in[9];
    const float* beta = (const float*)d_in[10];
    const int* ei = (const int*)d_in[11];
    float* out = (float*)d_out;

    cudaFuncSetAttribute(gmlp_kernel,
                         cudaFuncAttributeMaxDynamicSharedMemorySize, F_SMEM_BYTES);

    void* cntp = nullptr;
    cudaGetSymbolAddress(&cntp, g_cnt);
    cudaMemsetAsync(cntp, 0, NN * sizeof(int));
    void* statp = nullptr;
    cudaGetSymbolAddress(&statp, g_stats);
    cudaMemsetAsync(statp, 0, NLAYER * 2 * EMB * sizeof(float));
    void* flagp = nullptr;
    cudaGetSymbolAddress(&flagp, (const void*)g_chunkflag);
    cudaMemsetAsync(flagp, 0, NCHUNK * sizeof(int));

    float* statbase = (float*)statp;
    const int nblk = (NN + 63) / 64;   // 782 blocks

    hist_embed_kernel<<<(NE + 255) / 256, 256>>>(ei, x, Wemb);   // 0
    scan_kernel<<<NCHUNK, 1024>>>();                             // 1
    fill_kernel<<<(NE + 255) / 256, 256>>>(ei);                  // 2
    sgather_kernel<<<(NN * 32 + 255) / 256, 256>>>(ea);          // 3 (profiled)

    for (int l = 0; l < NLAYER; l++) {
        float* statsl = statbase + (size_t)l * 2 * EMB;
        gmlp_kernel<<<nblk, 256, F_SMEM_BYTES>>>(
            W1 + (size_t)l * EMB2 * EMB, b1 + (size_t)l * EMB2,
            W2 + (size_t)l * EMB * EMB2, b2 + (size_t)l * EMB,
            We + (size_t)l * EMB * BOND_F, be + (size_t)l * EMB, statsl);
        if (l < NLAYER - 1)
            norm_kernel<false><<<nblk, 256>>>(
                statsl, gamma + (size_t)l * EMB, beta + (size_t)l * EMB, nullptr);
        else
            norm_kernel<true><<<nblk, 256>>>(
                statsl, gamma + (size_t)l * EMB, beta + (size_t)l * EMB, out);
    }
}